// round 3
// baseline (speedup 1.0000x reference)
#include <cuda_runtime.h>
#include <math.h>

// ---------------- problem constants (fixed by setup_inputs) ----------------
#define Bq    32
#define Hq    56
#define Wq    56
#define Cq    384
#define NHq   6
#define HDq   64
#define WSq   7
#define NWq   49          // WS*WS
#define HIDq  1536
#define Ntok  (Hq*Wq)     // 3136
#define ROWS  (Bq*Ntok)   // 100352
#define LN_EPS 1e-5f

// ---------------- scratch (device globals; no allocation allowed) ----------
__device__ float g_xn[(size_t)ROWS * Cq];        // LN output (reused for LN2)
__device__ float g_qkv[(size_t)ROWS * 3 * Cq];   // qkv
__device__ float g_attnout[(size_t)ROWS * Cq];   // attention output (pre-proj)
__device__ float g_h1[(size_t)ROWS * HIDq];      // fc1 output
__device__ float g_h2[(size_t)ROWS * HIDq];      // dwconv+gelu output

// ---------------- LayerNorm: one block per row, 128 threads ----------------
__global__ __launch_bounds__(128) void ln_kernel(
    const float* __restrict__ x, const float* __restrict__ gamma,
    const float* __restrict__ beta, float* __restrict__ y)
{
    int row = blockIdx.x;
    const float* xr = x + (size_t)row * Cq;
    float* yr = y + (size_t)row * Cq;
    int tid = threadIdx.x;

    float v0 = xr[tid], v1 = xr[tid + 128], v2 = xr[tid + 256];
    float s  = v0 + v1 + v2;
    float s2 = v0*v0 + v1*v1 + v2*v2;

    // warp + block reduce (4 warps)
    #pragma unroll
    for (int o = 16; o > 0; o >>= 1) {
        s  += __shfl_down_sync(0xffffffffu, s,  o);
        s2 += __shfl_down_sync(0xffffffffu, s2, o);
    }
    __shared__ float sh[8];
    int wid = tid >> 5, lid = tid & 31;
    if (lid == 0) { sh[wid] = s; sh[wid + 4] = s2; }
    __syncthreads();
    if (tid == 0) {
        float ts = sh[0]+sh[1]+sh[2]+sh[3];
        float ts2 = sh[4]+sh[5]+sh[6]+sh[7];
        float mu = ts * (1.0f / Cq);
        float var = ts2 * (1.0f / Cq) - mu * mu;
        sh[0] = mu;
        sh[1] = rsqrtf(var + LN_EPS);
    }
    __syncthreads();
    float mu = sh[0], inv = sh[1];
    yr[tid]       = (v0 - mu) * inv * gamma[tid]       + beta[tid];
    yr[tid + 128] = (v1 - mu) * inv * gamma[tid + 128] + beta[tid + 128];
    yr[tid + 256] = (v2 - mu) * inv * gamma[tid + 256] + beta[tid + 256];
}

// ---------------- SGEMM 128x128x8, 256 threads, 8x8 microtile --------------
// C = A(MxK) @ B(KxN) [+ bias] [+ res].  M%128==0, N%128==0, K%8==0 assumed.
template<bool BIAS, bool RES>
__global__ __launch_bounds__(256) void sgemm_kernel(
    const float* __restrict__ A, const float* __restrict__ B,
    const float* __restrict__ bias, const float* __restrict__ res,
    float* __restrict__ C, int M, int N, int K)
{
    __shared__ float As[8][128];
    __shared__ float Bs[8][128];

    int tid = threadIdx.x;
    int bm = blockIdx.y * 128;
    int bn = blockIdx.x * 128;

    int a_row = tid >> 1;            // 0..127
    int a_col = (tid & 1) * 4;       // 0 or 4
    int b_row = tid >> 5;            // 0..7
    int b_col = (tid & 31) * 4;      // 0..124

    int tx = (tid & 15) * 8;         // 0..120
    int ty = (tid >> 4) * 8;         // 0..120

    const float* Aptr = A + (size_t)(bm + a_row) * K + a_col;
    const float* Bptr = B + (size_t)b_row * N + bn + b_col;

    float acc[8][8];
    #pragma unroll
    for (int i = 0; i < 8; i++)
        #pragma unroll
        for (int j = 0; j < 8; j++) acc[i][j] = 0.0f;

    for (int k0 = 0; k0 < K; k0 += 8) {
        float4 av = *(const float4*)(Aptr + k0);
        As[a_col + 0][a_row] = av.x;
        As[a_col + 1][a_row] = av.y;
        As[a_col + 2][a_row] = av.z;
        As[a_col + 3][a_row] = av.w;
        float4 bv = *(const float4*)(Bptr + (size_t)k0 * N);
        *(float4*)&Bs[b_row][b_col] = bv;
        __syncthreads();

        #pragma unroll
        for (int k = 0; k < 8; k++) {
            float4 a0 = *(const float4*)&As[k][ty];
            float4 a1 = *(const float4*)&As[k][ty + 4];
            float4 b0 = *(const float4*)&Bs[k][tx];
            float4 b1 = *(const float4*)&Bs[k][tx + 4];
            float ar[8] = {a0.x,a0.y,a0.z,a0.w,a1.x,a1.y,a1.z,a1.w};
            float br[8] = {b0.x,b0.y,b0.z,b0.w,b1.x,b1.y,b1.z,b1.w};
            #pragma unroll
            for (int i = 0; i < 8; i++)
                #pragma unroll
                for (int j = 0; j < 8; j++)
                    acc[i][j] = fmaf(ar[i], br[j], acc[i][j]);
        }
        __syncthreads();
    }

    float bb[8];
    if (BIAS) {
        #pragma unroll
        for (int j = 0; j < 8; j++) bb[j] = bias[bn + tx + j];
    }
    #pragma unroll
    for (int i = 0; i < 8; i++) {
        size_t off = (size_t)(bm + ty + i) * N + bn + tx;
        #pragma unroll
        for (int j = 0; j < 8; j++) {
            float v = acc[i][j];
            if (BIAS) v += bb[j];
            if (RES)  v += res[off + j];
            C[off + j] = v;
        }
    }
}

// ---------------- window attention: one block per (window, head) -----------
__global__ __launch_bounds__(128) void attn_kernel(
    const float* __restrict__ qkv, const float* __restrict__ rel_bias,
    float* __restrict__ out)
{
    int win  = blockIdx.x;            // 0..2047
    int head = blockIdx.y;            // 0..5
    int b  = win >> 6;
    int wi = win & 63;
    int wy = wi >> 3, wx = wi & 7;

    __shared__ float qs[NWq * 65];
    __shared__ float ks[NWq * 65];
    __shared__ float vs[NWq * 65];
    __shared__ float ss[NWq * 50];
    __shared__ int   growsh[NWq];

    int tid = threadIdx.x;
    if (tid < NWq) {
        int py = tid / 7, px = tid % 7;
        growsh[tid] = b * Ntok + (wy * 7 + py) * Wq + (wx * 7 + px);
    }
    __syncthreads();

    // load q,k,v for this head
    for (int idx = tid; idx < NWq * HDq; idx += 128) {
        int r = idx >> 6, d = idx & 63;
        size_t base = (size_t)growsh[r] * (3 * Cq) + head * HDq + d;
        qs[r * 65 + d] = qkv[base];
        ks[r * 65 + d] = qkv[base + Cq];
        vs[r * 65 + d] = qkv[base + 2 * Cq];
    }
    __syncthreads();

    // S = q k^T * scale + bias
    for (int idx = tid; idx < NWq * NWq; idx += 128) {
        int i = idx / NWq, j = idx - i * NWq;
        const float* qi = &qs[i * 65];
        const float* kj = &ks[j * 65];
        float acc = 0.0f;
        #pragma unroll 8
        for (int d = 0; d < HDq; d++) acc = fmaf(qi[d], kj[d], acc);
        int dy = i / 7 - j / 7 + 6;
        int dx = i % 7 - j % 7 + 6;
        ss[i * 50 + j] = acc * 0.125f + rel_bias[(dy * 13 + dx) * NHq + head];
    }
    __syncthreads();

    // softmax per row
    if (tid < NWq) {
        float* row = &ss[tid * 50];
        float m = -1e30f;
        for (int j = 0; j < NWq; j++) m = fmaxf(m, row[j]);
        float sum = 0.0f;
        for (int j = 0; j < NWq; j++) { float e = __expf(row[j] - m); row[j] = e; sum += e; }
        float r = 1.0f / sum;
        for (int j = 0; j < NWq; j++) row[j] *= r;
    }
    __syncthreads();

    // O = P v, scattered back window-reversed
    for (int idx = tid; idx < NWq * HDq; idx += 128) {
        int i = idx >> 6, d = idx & 63;
        const float* pi = &ss[i * 50];
        float acc = 0.0f;
        #pragma unroll 7
        for (int j = 0; j < NWq; j++) acc = fmaf(pi[j], vs[j * 65 + d], acc);
        out[(size_t)growsh[i] * Cq + head * HDq + d] = acc;
    }
}

// ---------------- depthwise 3x3 conv (NHWC) + bias + exact GELU ------------
__global__ __launch_bounds__(256) void dwconv_gelu_kernel(
    const float* __restrict__ h1, const float* __restrict__ w,
    const float* __restrict__ bias, float* __restrict__ h2)
{
    int idx = blockIdx.x * 256 + threadIdx.x;     // (pixel, c4) pairs
    int c4  = idx % (HIDq / 4);
    int pix = idx / (HIDq / 4);
    int xq = pix % Wq;
    int yq = (pix / Wq) % Hq;
    int bq = pix / Ntok;
    int c = c4 * 4;

    float4 acc = *(const float4*)(bias + c);
    #pragma unroll
    for (int dy = -1; dy <= 1; dy++) {
        int yy = yq + dy;
        if (yy < 0 || yy >= Hq) continue;
        #pragma unroll
        for (int dx = -1; dx <= 1; dx++) {
            int xx = xq + dx;
            if (xx < 0 || xx >= Wq) continue;
            size_t src = ((size_t)(bq * Ntok + yy * Wq + xx)) * HIDq + c;
            float4 v = *(const float4*)(h1 + src);
            int wk = (dy + 1) * 3 + (dx + 1);
            acc.x = fmaf(v.x, w[(c + 0) * 9 + wk], acc.x);
            acc.y = fmaf(v.y, w[(c + 1) * 9 + wk], acc.y);
            acc.z = fmaf(v.z, w[(c + 2) * 9 + wk], acc.z);
            acc.w = fmaf(v.w, w[(c + 3) * 9 + wk], acc.w);
        }
    }
    // exact GELU
    const float is2 = 0.70710678118654752f;
    acc.x = 0.5f * acc.x * (1.0f + erff(acc.x * is2));
    acc.y = 0.5f * acc.y * (1.0f + erff(acc.y * is2));
    acc.z = 0.5f * acc.z * (1.0f + erff(acc.z * is2));
    acc.w = 0.5f * acc.w * (1.0f + erff(acc.w * is2));
    *(float4*)(h2 + (size_t)pix * HIDq + c) = acc;
}

// ---------------- launch ----------------------------------------------------
extern "C" void kernel_launch(void* const* d_in, const int* in_sizes, int n_in,
                              void* d_out, int out_size)
{
    const float* x        = (const float*)d_in[0];
    const float* gamma1   = (const float*)d_in[1];
    const float* beta1    = (const float*)d_in[2];
    const float* w_qkv    = (const float*)d_in[3];
    const float* w_proj   = (const float*)d_in[4];
    const float* b_proj   = (const float*)d_in[5];
    const float* rel_bias = (const float*)d_in[6];
    const float* gamma2   = (const float*)d_in[7];
    const float* beta2    = (const float*)d_in[8];
    const float* w_fc1    = (const float*)d_in[9];
    const float* b_fc1    = (const float*)d_in[10];
    const float* w_dw     = (const float*)d_in[11];
    const float* b_dw     = (const float*)d_in[12];
    const float* w_fc2    = (const float*)d_in[13];
    const float* b_fc2    = (const float*)d_in[14];
    float* out = (float*)d_out;

    float *xn, *qkv, *attnout, *h1, *h2;
    cudaGetSymbolAddress((void**)&xn,      g_xn);
    cudaGetSymbolAddress((void**)&qkv,     g_qkv);
    cudaGetSymbolAddress((void**)&attnout, g_attnout);
    cudaGetSymbolAddress((void**)&h1,      g_h1);
    cudaGetSymbolAddress((void**)&h2,      g_h2);

    // 1. LN1
    ln_kernel<<<ROWS, 128>>>(x, gamma1, beta1, xn);

    // 2. QKV gemm: (100352,384) @ (384,1152)
    {
        dim3 grid((3 * Cq) / 128, ROWS / 128);
        sgemm_kernel<false, false><<<grid, 256>>>(xn, w_qkv, nullptr, nullptr,
                                                  qkv, ROWS, 3 * Cq, Cq);
    }

    // 3. window attention
    {
        dim3 grid(Bq * 64, NHq);
        attn_kernel<<<grid, 128>>>(qkv, rel_bias, attnout);
    }

    // 4. proj + bias + residual(x) -> d_out
    {
        dim3 grid(Cq / 128, ROWS / 128);
        sgemm_kernel<true, true><<<grid, 256>>>(attnout, w_proj, b_proj, x,
                                                out, ROWS, Cq, Cq);
    }

    // 5. LN2 on d_out
    ln_kernel<<<ROWS, 128>>>(out, gamma2, beta2, xn);

    // 6. fc1: (100352,384) @ (384,1536) + b
    {
        dim3 grid(HIDq / 128, ROWS / 128);
        sgemm_kernel<true, false><<<grid, 256>>>(xn, w_fc1, b_fc1, nullptr,
                                                 h1, ROWS, HIDq, Cq);
    }

    // 7. depthwise 3x3 + bias + GELU
    {
        int total = ROWS * (HIDq / 4);
        dwconv_gelu_kernel<<<total / 256, 256>>>(h1, w_dw, b_dw, h2);
    }

    // 8. fc2 + bias + residual(d_out) -> d_out
    {
        dim3 grid(Cq / 128, ROWS / 128);
        sgemm_kernel<true, true><<<grid, 256>>>(h2, w_fc2, b_fc2, out,
                                                out, ROWS, Cq, HIDq);
    }
}

// round 4
// speedup vs baseline: 1.1814x; 1.1814x over previous
#include <cuda_runtime.h>
#include <math.h>
#include <stdint.h>

// ---------------- problem constants (fixed by setup_inputs) ----------------
#define Bq    32
#define Hq    56
#define Wq    56
#define Cq    384
#define NHq   6
#define HDq   64
#define WSq   7
#define NWq   49          // WS*WS
#define HIDq  1536
#define Ntok  (Hq*Wq)     // 3136
#define ROWS  (Bq*Ntok)   // 100352
#define LN_EPS 1e-5f

// ---------------- scratch (device globals; no allocation allowed) ----------
__device__ float g_xn[(size_t)ROWS * Cq];        // LN output (reused for LN2)
__device__ float g_qkv[(size_t)ROWS * 3 * Cq];   // qkv
__device__ float g_attnout[(size_t)ROWS * Cq];   // attention output (pre-proj)
__device__ float g_h1[(size_t)ROWS * HIDq];      // fc1 output
__device__ float g_h2[(size_t)ROWS * HIDq];      // dwconv+gelu output

// ---------------- LayerNorm: one block per row, 128 threads ----------------
__global__ __launch_bounds__(128) void ln_kernel(
    const float* __restrict__ x, const float* __restrict__ gamma,
    const float* __restrict__ beta, float* __restrict__ y)
{
    int row = blockIdx.x;
    const float* xr = x + (size_t)row * Cq;
    float* yr = y + (size_t)row * Cq;
    int tid = threadIdx.x;

    float v0 = xr[tid], v1 = xr[tid + 128], v2 = xr[tid + 256];
    float s  = v0 + v1 + v2;
    float s2 = v0*v0 + v1*v1 + v2*v2;

    #pragma unroll
    for (int o = 16; o > 0; o >>= 1) {
        s  += __shfl_down_sync(0xffffffffu, s,  o);
        s2 += __shfl_down_sync(0xffffffffu, s2, o);
    }
    __shared__ float sh[8];
    int wid = tid >> 5, lid = tid & 31;
    if (lid == 0) { sh[wid] = s; sh[wid + 4] = s2; }
    __syncthreads();
    if (tid == 0) {
        float ts = sh[0]+sh[1]+sh[2]+sh[3];
        float ts2 = sh[4]+sh[5]+sh[6]+sh[7];
        float mu = ts * (1.0f / Cq);
        float var = ts2 * (1.0f / Cq) - mu * mu;
        sh[0] = mu;
        sh[1] = rsqrtf(var + LN_EPS);
    }
    __syncthreads();
    float mu = sh[0], inv = sh[1];
    yr[tid]       = (v0 - mu) * inv * gamma[tid]       + beta[tid];
    yr[tid + 128] = (v1 - mu) * inv * gamma[tid + 128] + beta[tid + 128];
    yr[tid + 256] = (v2 - mu) * inv * gamma[tid + 256] + beta[tid + 256];
}

// ---------------- TF32 tensor-core GEMM -------------------------------------
// C = A(MxK) @ B(KxN) [+ bias] [+ res].  M%128==0, N%128==0, K%16==0.
// CTA tile 128x128x16, 256 threads = 8 warps, warp tile 64x32.
// Shared memory holds tiles pre-permuted into mma fragment order so that
// each thread's A fragment is one LDS.128 and B fragment one LDS.64.

__device__ __forceinline__ float f2tf32(float x) {
    uint32_t r;
    asm volatile("cvt.rna.tf32.f32 %0, %1;" : "=r"(r) : "f"(x));
    return __uint_as_float(r);
}

__device__ __forceinline__ void mma_tf32(float c[4],
    uint32_t a0, uint32_t a1, uint32_t a2, uint32_t a3,
    uint32_t b0, uint32_t b1)
{
    asm volatile(
        "mma.sync.aligned.m16n8k8.row.col.f32.tf32.tf32.f32 "
        "{%0,%1,%2,%3}, {%4,%5,%6,%7}, {%8,%9}, {%0,%1,%2,%3};\n"
        : "+f"(c[0]), "+f"(c[1]), "+f"(c[2]), "+f"(c[3])
        : "r"(a0), "r"(a1), "r"(a2), "r"(a3), "r"(b0), "r"(b1));
}

template<bool BIAS, bool RES>
__global__ __launch_bounds__(256) void tf32_gemm_kernel(
    const float* __restrict__ A, const float* __restrict__ B,
    const float* __restrict__ bias, const float* __restrict__ res,
    float* __restrict__ C, int M, int N, int K)
{
    // fragment-order layouts:
    // As[buf]: float idx = (k8*8 + m16)*128 + lane*4 + reg      (2048 floats)
    // Bs[buf]: float idx = (k8*16 + n8)*64 + lane*2 + reg       (2048 floats)
    __shared__ float As[2][2048];
    __shared__ float Bs[2][2048];

    int tid  = threadIdx.x;
    int lane = tid & 31;
    int warp = tid >> 5;
    int warp_m = warp & 1;        // 2 -> 64-row halves
    int warp_n = warp >> 1;       // 4 -> 32-col quarters
    int g   = lane >> 2;
    int tig = lane & 3;

    int bm = blockIdx.y * 128;
    int bn = blockIdx.x * 128;

    // ---- global loaders: warps 0-3 load A (row each), warps 4-7 load B ----
    bool isA = tid < 128;
    const float* gptr;
    int abase = 0, bbase = 0;
    if (isA) {
        int row = tid;                              // 0..127 within tile
        gptr = A + (size_t)(bm + row) * K;
        int m16 = row >> 4, r16 = row & 15;
        abase = m16 * 128 + (r16 & 7) * 16 + (r16 >> 3);
    } else {
        int t2 = tid - 128;
        int krow  = t2 >> 3;                        // 0..15
        int ncol0 = (t2 & 7) * 16;                  // 0..112
        gptr = B + (size_t)krow * N + bn + ncol0;
        int kk = krow & 7;
        bbase = (krow >> 3) * 1024 + (ncol0 >> 3) * 64 + (kk & 3) * 2 + (kk >> 2);
    }

    float acc[4][4][4];
    #pragma unroll
    for (int i = 0; i < 4; i++)
        #pragma unroll
        for (int j = 0; j < 4; j++)
            #pragma unroll
            for (int r = 0; r < 4; r++) acc[i][j][r] = 0.0f;

    int T = K / 16;
    float4 ld[4];

    // prologue: load tile 0
    if (isA) {
        #pragma unroll
        for (int c = 0; c < 4; c++) ld[c] = *(const float4*)(gptr + c * 4);
    } else {
        #pragma unroll
        for (int c = 0; c < 4; c++) ld[c] = *(const float4*)(gptr + c * 4);
    }
    // store tile 0 (with tf32 rounding)
    {
        float* dst = isA ? As[0] : Bs[0];
        #pragma unroll
        for (int c = 0; c < 4; c++) {
            float v[4] = {ld[c].x, ld[c].y, ld[c].z, ld[c].w};
            #pragma unroll
            for (int j = 0; j < 4; j++) {
                int off = isA ? (abase + (c >> 1) * 1024 + (c & 1) * 2 + j * 4)
                              : (bbase + (c >> 1) * 64 + ((c & 1) * 4 + j) * 8);
                dst[off] = f2tf32(v[j]);
            }
        }
    }
    __syncthreads();

    for (int t = 0; t < T; t++) {
        int buf = t & 1;
        // prefetch next tile into registers
        if (t + 1 < T) {
            int k0 = (t + 1) * 16;
            if (isA) {
                #pragma unroll
                for (int c = 0; c < 4; c++)
                    ld[c] = *(const float4*)(gptr + k0 + c * 4);
            } else {
                #pragma unroll
                for (int c = 0; c < 4; c++)
                    ld[c] = *(const float4*)(gptr + (size_t)k0 * N + c * 4);
            }
        }

        // ---- compute current buffer: 2 k8-steps ----
        #pragma unroll
        for (int k8 = 0; k8 < 2; k8++) {
            uint32_t afr[4][4];
            #pragma unroll
            for (int mi = 0; mi < 4; mi++) {
                float4 v = *(const float4*)&As[buf][(k8 * 8 + warp_m * 4 + mi) * 128 + lane * 4];
                afr[mi][0] = __float_as_uint(v.x);
                afr[mi][1] = __float_as_uint(v.y);
                afr[mi][2] = __float_as_uint(v.z);
                afr[mi][3] = __float_as_uint(v.w);
            }
            uint32_t bfr[4][2];
            #pragma unroll
            for (int ni = 0; ni < 4; ni++) {
                float2 v = *(const float2*)&Bs[buf][(k8 * 16 + warp_n * 4 + ni) * 64 + lane * 2];
                bfr[ni][0] = __float_as_uint(v.x);
                bfr[ni][1] = __float_as_uint(v.y);
            }
            #pragma unroll
            for (int mi = 0; mi < 4; mi++)
                #pragma unroll
                for (int ni = 0; ni < 4; ni++)
                    mma_tf32(acc[mi][ni], afr[mi][0], afr[mi][1], afr[mi][2], afr[mi][3],
                             bfr[ni][0], bfr[ni][1]);
        }

        // ---- store prefetched tile into the other buffer ----
        if (t + 1 < T) {
            float* dst = isA ? As[buf ^ 1] : Bs[buf ^ 1];
            #pragma unroll
            for (int c = 0; c < 4; c++) {
                float v[4] = {ld[c].x, ld[c].y, ld[c].z, ld[c].w};
                #pragma unroll
                for (int j = 0; j < 4; j++) {
                    int off = isA ? (abase + (c >> 1) * 1024 + (c & 1) * 2 + j * 4)
                                  : (bbase + (c >> 1) * 64 + ((c & 1) * 4 + j) * 8);
                    dst[off] = f2tf32(v[j]);
                }
            }
            __syncthreads();
        }
    }

    // ---- epilogue ----
    #pragma unroll
    for (int mi = 0; mi < 4; mi++) {
        int row0 = bm + warp_m * 64 + mi * 16 + g;
        #pragma unroll
        for (int ni = 0; ni < 4; ni++) {
            int col = bn + warp_n * 32 + ni * 8 + tig * 2;
            size_t off0 = (size_t)row0 * N + col;
            size_t off1 = off0 + (size_t)8 * N;
            float c0 = acc[mi][ni][0], c1 = acc[mi][ni][1];
            float c2 = acc[mi][ni][2], c3 = acc[mi][ni][3];
            if (BIAS) {
                float b0 = bias[col], b1 = bias[col + 1];
                c0 += b0; c1 += b1; c2 += b0; c3 += b1;
            }
            if (RES) {
                float2 r0 = *(const float2*)(res + off0);
                float2 r1 = *(const float2*)(res + off1);
                c0 += r0.x; c1 += r0.y; c2 += r1.x; c3 += r1.y;
            }
            *(float2*)(C + off0) = make_float2(c0, c1);
            *(float2*)(C + off1) = make_float2(c2, c3);
        }
    }
}

// ---------------- window attention: one block per (window, head) -----------
__global__ __launch_bounds__(128) void attn_kernel(
    const float* __restrict__ qkv, const float* __restrict__ rel_bias,
    float* __restrict__ out)
{
    int win  = blockIdx.x;            // 0..2047
    int head = blockIdx.y;            // 0..5
    int b  = win >> 6;
    int wi = win & 63;
    int wy = wi >> 3, wx = wi & 7;

    __shared__ float qs[NWq * 65];
    __shared__ float ks[NWq * 65];
    __shared__ float vs[NWq * 65];
    __shared__ float ss[NWq * 50];
    __shared__ int   growsh[NWq];

    int tid = threadIdx.x;
    if (tid < NWq) {
        int py = tid / 7, px = tid % 7;
        growsh[tid] = b * Ntok + (wy * 7 + py) * Wq + (wx * 7 + px);
    }
    __syncthreads();

    for (int idx = tid; idx < NWq * HDq; idx += 128) {
        int r = idx >> 6, d = idx & 63;
        size_t base = (size_t)growsh[r] * (3 * Cq) + head * HDq + d;
        qs[r * 65 + d] = qkv[base];
        ks[r * 65 + d] = qkv[base + Cq];
        vs[r * 65 + d] = qkv[base + 2 * Cq];
    }
    __syncthreads();

    for (int idx = tid; idx < NWq * NWq; idx += 128) {
        int i = idx / NWq, j = idx - i * NWq;
        const float* qi = &qs[i * 65];
        const float* kj = &ks[j * 65];
        float acc = 0.0f;
        #pragma unroll 8
        for (int d = 0; d < HDq; d++) acc = fmaf(qi[d], kj[d], acc);
        int dy = i / 7 - j / 7 + 6;
        int dx = i % 7 - j % 7 + 6;
        ss[i * 50 + j] = acc * 0.125f + rel_bias[(dy * 13 + dx) * NHq + head];
    }
    __syncthreads();

    if (tid < NWq) {
        float* row = &ss[tid * 50];
        float m = -1e30f;
        for (int j = 0; j < NWq; j++) m = fmaxf(m, row[j]);
        float sum = 0.0f;
        for (int j = 0; j < NWq; j++) { float e = __expf(row[j] - m); row[j] = e; sum += e; }
        float r = 1.0f / sum;
        for (int j = 0; j < NWq; j++) row[j] *= r;
    }
    __syncthreads();

    for (int idx = tid; idx < NWq * HDq; idx += 128) {
        int i = idx >> 6, d = idx & 63;
        const float* pi = &ss[i * 50];
        float acc = 0.0f;
        #pragma unroll 7
        for (int j = 0; j < NWq; j++) acc = fmaf(pi[j], vs[j * 65 + d], acc);
        out[(size_t)growsh[i] * Cq + head * HDq + d] = acc;
    }
}

// ---------------- depthwise 3x3 conv (NHWC) + bias + exact GELU ------------
__global__ __launch_bounds__(256) void dwconv_gelu_kernel(
    const float* __restrict__ h1, const float* __restrict__ w,
    const float* __restrict__ bias, float* __restrict__ h2)
{
    int idx = blockIdx.x * 256 + threadIdx.x;     // (pixel, c4) pairs
    int c4  = idx % (HIDq / 4);
    int pix = idx / (HIDq / 4);
    int xq = pix % Wq;
    int yq = (pix / Wq) % Hq;
    int bq = pix / Ntok;
    int c = c4 * 4;

    float4 acc = *(const float4*)(bias + c);
    #pragma unroll
    for (int dy = -1; dy <= 1; dy++) {
        int yy = yq + dy;
        if (yy < 0 || yy >= Hq) continue;
        #pragma unroll
        for (int dx = -1; dx <= 1; dx++) {
            int xx = xq + dx;
            if (xx < 0 || xx >= Wq) continue;
            size_t src = ((size_t)(bq * Ntok + yy * Wq + xx)) * HIDq + c;
            float4 v = *(const float4*)(h1 + src);
            int wk = (dy + 1) * 3 + (dx + 1);
            acc.x = fmaf(v.x, w[(c + 0) * 9 + wk], acc.x);
            acc.y = fmaf(v.y, w[(c + 1) * 9 + wk], acc.y);
            acc.z = fmaf(v.z, w[(c + 2) * 9 + wk], acc.z);
            acc.w = fmaf(v.w, w[(c + 3) * 9 + wk], acc.w);
        }
    }
    const float is2 = 0.70710678118654752f;
    acc.x = 0.5f * acc.x * (1.0f + erff(acc.x * is2));
    acc.y = 0.5f * acc.y * (1.0f + erff(acc.y * is2));
    acc.z = 0.5f * acc.z * (1.0f + erff(acc.z * is2));
    acc.w = 0.5f * acc.w * (1.0f + erff(acc.w * is2));
    *(float4*)(h2 + (size_t)pix * HIDq + c) = acc;
}

// ---------------- launch ----------------------------------------------------
extern "C" void kernel_launch(void* const* d_in, const int* in_sizes, int n_in,
                              void* d_out, int out_size)
{
    const float* x        = (const float*)d_in[0];
    const float* gamma1   = (const float*)d_in[1];
    const float* beta1    = (const float*)d_in[2];
    const float* w_qkv    = (const float*)d_in[3];
    const float* w_proj   = (const float*)d_in[4];
    const float* b_proj   = (const float*)d_in[5];
    const float* rel_bias = (const float*)d_in[6];
    const float* gamma2   = (const float*)d_in[7];
    const float* beta2    = (const float*)d_in[8];
    const float* w_fc1    = (const float*)d_in[9];
    const float* b_fc1    = (const float*)d_in[10];
    const float* w_dw     = (const float*)d_in[11];
    const float* b_dw     = (const float*)d_in[12];
    const float* w_fc2    = (const float*)d_in[13];
    const float* b_fc2    = (const float*)d_in[14];
    float* out = (float*)d_out;

    float *xn, *qkv, *attnout, *h1, *h2;
    cudaGetSymbolAddress((void**)&xn,      g_xn);
    cudaGetSymbolAddress((void**)&qkv,     g_qkv);
    cudaGetSymbolAddress((void**)&attnout, g_attnout);
    cudaGetSymbolAddress((void**)&h1,      g_h1);
    cudaGetSymbolAddress((void**)&h2,      g_h2);

    // 1. LN1
    ln_kernel<<<ROWS, 128>>>(x, gamma1, beta1, xn);

    // 2. QKV gemm: (100352,384) @ (384,1152)
    {
        dim3 grid((3 * Cq) / 128, ROWS / 128);
        tf32_gemm_kernel<false, false><<<grid, 256>>>(xn, w_qkv, nullptr, nullptr,
                                                      qkv, ROWS, 3 * Cq, Cq);
    }

    // 3. window attention
    {
        dim3 grid(Bq * 64, NHq);
        attn_kernel<<<grid, 128>>>(qkv, rel_bias, attnout);
    }

    // 4. proj + bias + residual(x) -> d_out
    {
        dim3 grid(Cq / 128, ROWS / 128);
        tf32_gemm_kernel<true, true><<<grid, 256>>>(attnout, w_proj, b_proj, x,
                                                    out, ROWS, Cq, Cq);
    }

    // 5. LN2 on d_out
    ln_kernel<<<ROWS, 128>>>(out, gamma2, beta2, xn);

    // 6. fc1: (100352,384) @ (384,1536) + b
    {
        dim3 grid(HIDq / 128, ROWS / 128);
        tf32_gemm_kernel<true, false><<<grid, 256>>>(xn, w_fc1, b_fc1, nullptr,
                                                     h1, ROWS, HIDq, Cq);
    }

    // 7. depthwise 3x3 + bias + GELU
    {
        int total = ROWS * (HIDq / 4);
        dwconv_gelu_kernel<<<total / 256, 256>>>(h1, w_dw, b_dw, h2);
    }

    // 8. fc2 + bias + residual(d_out) -> d_out
    {
        dim3 grid(Cq / 128, ROWS / 128);
        tf32_gemm_kernel<true, true><<<grid, 256>>>(h2, w_fc2, b_fc2, out,
                                                    out, ROWS, Cq, HIDq);
    }
}

// round 5
// speedup vs baseline: 2.9196x; 2.4713x over previous
#include <cuda_runtime.h>
#include <cuda_bf16.h>
#include <math.h>
#include <stdint.h>

typedef __nv_bfloat16 bf16;

// ---------------- problem constants ----------------
#define Bq    32
#define Hq    56
#define Wq    56
#define Cq    384
#define NHq   6
#define HDq   64
#define NWq   49
#define HIDq  1536
#define Ntok  (Hq*Wq)     // 3136
#define ROWS  (Bq*Ntok)   // 100352
#define LN_EPS 1e-5f

// ---------------- scratch (device globals) ----------------
__device__ bf16 g_xn[(size_t)ROWS * Cq];
__device__ bf16 g_qkv[(size_t)ROWS * 3 * Cq];
__device__ bf16 g_attnout[(size_t)ROWS * Cq];
__device__ bf16 g_h1[(size_t)ROWS * HIDq];
__device__ bf16 g_h2[(size_t)ROWS * HIDq];
__device__ bf16 g_wqkv[Cq * 3 * Cq];
__device__ bf16 g_wproj[Cq * Cq];
__device__ bf16 g_wfc1[Cq * HIDq];
__device__ bf16 g_wfc2[HIDq * Cq];

// ---------------- small helpers ----------------
__device__ __forceinline__ uint32_t smem_cast(const void* p) {
    return (uint32_t)__cvta_generic_to_shared(p);
}
__device__ __forceinline__ void cp16(uint32_t s, const void* g) {
    asm volatile("cp.async.cg.shared.global [%0], [%1], 16;\n" :: "r"(s), "l"(g));
}
__device__ __forceinline__ void cp_commit() {
    asm volatile("cp.async.commit_group;\n");
}
template<int N> __device__ __forceinline__ void cp_wait() {
    asm volatile("cp.async.wait_group %0;\n" :: "n"(N));
}
__device__ __forceinline__ void ldsm4(uint32_t* r, uint32_t a) {
    asm volatile("ldmatrix.sync.aligned.m8n8.x4.shared.b16 {%0,%1,%2,%3}, [%4];"
        : "=r"(r[0]), "=r"(r[1]), "=r"(r[2]), "=r"(r[3]) : "r"(a));
}
__device__ __forceinline__ void ldsm4t(uint32_t* r, uint32_t a) {
    asm volatile("ldmatrix.sync.aligned.m8n8.x4.trans.shared.b16 {%0,%1,%2,%3}, [%4];"
        : "=r"(r[0]), "=r"(r[1]), "=r"(r[2]), "=r"(r[3]) : "r"(a));
}
__device__ __forceinline__ void mma_bf16(float* c, const uint32_t* a, uint32_t b0, uint32_t b1) {
    asm volatile(
        "mma.sync.aligned.m16n8k16.row.col.f32.bf16.bf16.f32 "
        "{%0,%1,%2,%3}, {%4,%5,%6,%7}, {%8,%9}, {%0,%1,%2,%3};\n"
        : "+f"(c[0]), "+f"(c[1]), "+f"(c[2]), "+f"(c[3])
        : "r"(a[0]), "r"(a[1]), "r"(a[2]), "r"(a[3]), "r"(b0), "r"(b1));
}

// ---------------- fp32 -> bf16 convert ----------------
__global__ __launch_bounds__(256) void cvt_kernel(const float* __restrict__ s,
                                                  bf16* __restrict__ d, int n) {
    int i = blockIdx.x * 256 + threadIdx.x;
    if (i < n) d[i] = __float2bfloat16(s[i]);
}

// ---------------- LayerNorm (fp32 in, bf16 out) ----------------
__global__ __launch_bounds__(128) void ln_kernel(
    const float* __restrict__ x, const float* __restrict__ gamma,
    const float* __restrict__ beta, bf16* __restrict__ y)
{
    int row = blockIdx.x;
    const float* xr = x + (size_t)row * Cq;
    bf16* yr = y + (size_t)row * Cq;
    int tid = threadIdx.x;

    float v0 = xr[tid], v1 = xr[tid + 128], v2 = xr[tid + 256];
    float s  = v0 + v1 + v2;
    float s2 = v0*v0 + v1*v1 + v2*v2;
    #pragma unroll
    for (int o = 16; o > 0; o >>= 1) {
        s  += __shfl_down_sync(0xffffffffu, s,  o);
        s2 += __shfl_down_sync(0xffffffffu, s2, o);
    }
    __shared__ float sh[8];
    int wid = tid >> 5, lid = tid & 31;
    if (lid == 0) { sh[wid] = s; sh[wid + 4] = s2; }
    __syncthreads();
    if (tid == 0) {
        float ts = sh[0]+sh[1]+sh[2]+sh[3];
        float ts2 = sh[4]+sh[5]+sh[6]+sh[7];
        float mu = ts * (1.0f / Cq);
        float var = ts2 * (1.0f / Cq) - mu * mu;
        sh[0] = mu;
        sh[1] = rsqrtf(var + LN_EPS);
    }
    __syncthreads();
    float mu = sh[0], inv = sh[1];
    yr[tid]       = __float2bfloat16((v0 - mu) * inv * gamma[tid]       + beta[tid]);
    yr[tid + 128] = __float2bfloat16((v1 - mu) * inv * gamma[tid + 128] + beta[tid + 128]);
    yr[tid + 256] = __float2bfloat16((v2 - mu) * inv * gamma[tid + 256] + beta[tid + 256]);
}

// ---------------- bf16 tensor-core GEMM -------------------------------------
// C = A(MxK) @ B(KxN) [+ bias] [+ res].  M%128==0, N%128==0, K%32==0.
// CTA 128x128x32, 256 threads (8 warps, 64x32 warp tiles), 3-stage cp.async,
// swizzled smem + ldmatrix, mma.m16n8k16.bf16. OT = float or bf16 output.
template<typename OT, bool BIAS, bool RES>
__global__ __launch_bounds__(256, 2) void bf16_gemm_kernel(
    const bf16* __restrict__ A, const bf16* __restrict__ B,
    const float* __restrict__ bias, const float* __restrict__ res,
    OT* __restrict__ C, int M, int N, int K)
{
    // per stage: A 128x32 bf16 (8KB, 64B rows, swizzled) then B 32x128 (8KB, 256B rows)
    __shared__ __align__(16) char smem[3 * 16384];
    uint32_t sbase = smem_cast(smem);

    int tid = threadIdx.x, lane = tid & 31, warp = tid >> 5;
    int warp_m = warp & 1, warp_n = warp >> 1;
    int bm = blockIdx.y * 128, bn = blockIdx.x * 128;

    // ---- global->smem assignments (cp.async, 16B chunks) ----
    int arow0 = tid >> 2;            // 0..63
    int ag    = tid & 3;             // k-group (8 bf16 each)
    const bf16* gA0 = A + (size_t)(bm + arow0) * K + ag * 8;
    const bf16* gA1 = gA0 + (size_t)64 * K;
    uint32_t sA0 = arow0 * 64 + ((ag ^ ((arow0 >> 1) & 3)) << 4);
    int arow1 = arow0 + 64;
    uint32_t sA1 = arow1 * 64 + ((ag ^ ((arow1 >> 1) & 3)) << 4);

    int bk0 = tid >> 4;              // 0..15
    int bn8 = tid & 15;              // n-group (8 bf16 each)
    const bf16* gB0 = B + (size_t)bk0 * N + bn + bn8 * 8;
    const bf16* gB1 = gB0 + (size_t)16 * N;
    uint32_t sB0 = 8192 + bk0 * 256 + (((bn8 & 8) | ((bn8 & 7) ^ (bk0 & 7))) << 4);
    int bk1 = bk0 + 16;
    uint32_t sB1 = 8192 + bk1 * 256 + (((bn8 & 8) | ((bn8 & 7) ^ (bk1 & 7))) << 4);

    // ---- ldmatrix per-lane offsets ----
    int l7 = lane & 7, lb = (lane >> 3) & 1, lh = (lane >> 4) & 1;
    int arow = warp_m * 64 + l7 + lb * 8;            // mi=0; +1024B per mi
    uint32_t aoff[2];
    #pragma unroll
    for (int s = 0; s < 2; s++) {
        int g = s * 2 + lh;
        aoff[s] = arow * 64 + ((g ^ ((arow >> 1) & 3)) << 4);
    }
    int bkl = l7 + lb * 8;                           // k within k16; s adds 4096B
    uint32_t boff[2];
    #pragma unroll
    for (int p = 0; p < 2; p++) {
        int n8 = warp_n * 4 + p * 2 + lh;
        boff[p] = 8192 + bkl * 256 + (((n8 & 8) | ((n8 & 7) ^ (bkl & 7))) << 4);
    }

    float acc[4][4][4];
    #pragma unroll
    for (int i = 0; i < 4; i++)
        #pragma unroll
        for (int j = 0; j < 4; j++)
            #pragma unroll
            for (int r = 0; r < 4; r++) acc[i][j][r] = 0.0f;

    int T = K / 32;
    auto issue = [&](int t, int st) {
        uint32_t sb = sbase + st * 16384;
        cp16(sb + sA0, gA0 + t * 32);
        cp16(sb + sA1, gA1 + t * 32);
        cp16(sb + sB0, gB0 + (size_t)t * 32 * N);
        cp16(sb + sB1, gB1 + (size_t)t * 32 * N);
    };

    issue(0, 0); cp_commit();
    issue(1, 1); cp_commit();
    cp_wait<1>(); __syncthreads();

    for (int t = 0; t < T; t++) {
        int st = t - (t / 3) * 3;
        if (t + 2 < T) issue(t + 2, (t + 2) % 3);
        cp_commit();

        uint32_t sb = sbase + st * 16384;
        #pragma unroll
        for (int s = 0; s < 2; s++) {
            uint32_t a[4][4], b[2][4];
            #pragma unroll
            for (int mi = 0; mi < 4; mi++) ldsm4(a[mi], sb + aoff[s] + mi * 1024);
            #pragma unroll
            for (int p = 0; p < 2; p++) ldsm4t(b[p], sb + boff[p] + s * 4096);
            #pragma unroll
            for (int mi = 0; mi < 4; mi++) {
                mma_bf16(acc[mi][0], a[mi], b[0][0], b[0][1]);
                mma_bf16(acc[mi][1], a[mi], b[0][2], b[0][3]);
                mma_bf16(acc[mi][2], a[mi], b[1][0], b[1][1]);
                mma_bf16(acc[mi][3], a[mi], b[1][2], b[1][3]);
            }
        }
        cp_wait<1>(); __syncthreads();
    }

    // ---- epilogue ----
    int g = lane >> 2, tig = lane & 3;
    #pragma unroll
    for (int mi = 0; mi < 4; mi++) {
        int row0 = bm + warp_m * 64 + mi * 16 + g;
        #pragma unroll
        for (int ni = 0; ni < 4; ni++) {
            int col = bn + warp_n * 32 + ni * 8 + tig * 2;
            size_t off0 = (size_t)row0 * N + col;
            size_t off1 = off0 + (size_t)8 * N;
            float c0 = acc[mi][ni][0], c1 = acc[mi][ni][1];
            float c2 = acc[mi][ni][2], c3 = acc[mi][ni][3];
            if (BIAS) {
                float b0 = bias[col], b1 = bias[col + 1];
                c0 += b0; c1 += b1; c2 += b0; c3 += b1;
            }
            if (RES) {
                float2 r0 = *(const float2*)(res + off0);
                float2 r1 = *(const float2*)(res + off1);
                c0 += r0.x; c1 += r0.y; c2 += r1.x; c3 += r1.y;
            }
            if constexpr (sizeof(OT) == 4) {
                *(float2*)((float*)C + off0) = make_float2(c0, c1);
                *(float2*)((float*)C + off1) = make_float2(c2, c3);
            } else {
                __nv_bfloat162 v0, v1;
                v0.x = __float2bfloat16(c0); v0.y = __float2bfloat16(c1);
                v1.x = __float2bfloat16(c2); v1.y = __float2bfloat16(c3);
                *(__nv_bfloat162*)((bf16*)C + off0) = v0;
                *(__nv_bfloat162*)((bf16*)C + off1) = v1;
            }
        }
    }
}

// ---------------- window attention (bf16 qkv in, bf16 out) -----------------
__global__ __launch_bounds__(128) void attn_kernel(
    const bf16* __restrict__ qkv, const float* __restrict__ rel_bias,
    bf16* __restrict__ out)
{
    int win  = blockIdx.x;
    int head = blockIdx.y;
    int b  = win >> 6;
    int wi = win & 63;
    int wy = wi >> 3, wx = wi & 7;

    __shared__ float qs[NWq * 65];
    __shared__ float ks[NWq * 65];
    __shared__ float vs[NWq * 65];
    __shared__ float ss[NWq * 50];
    __shared__ int   growsh[NWq];

    int tid = threadIdx.x;
    if (tid < NWq) {
        int py = tid / 7, px = tid % 7;
        growsh[tid] = b * Ntok + (wy * 7 + py) * Wq + (wx * 7 + px);
    }
    __syncthreads();

    for (int idx = tid; idx < NWq * HDq; idx += 128) {
        int r = idx >> 6, d = idx & 63;
        size_t base = (size_t)growsh[r] * (3 * Cq) + head * HDq + d;
        qs[r * 65 + d] = __bfloat162float(qkv[base]);
        ks[r * 65 + d] = __bfloat162float(qkv[base + Cq]);
        vs[r * 65 + d] = __bfloat162float(qkv[base + 2 * Cq]);
    }
    __syncthreads();

    for (int idx = tid; idx < NWq * NWq; idx += 128) {
        int i = idx / NWq, j = idx - i * NWq;
        const float* qi = &qs[i * 65];
        const float* kj = &ks[j * 65];
        float acc = 0.0f;
        #pragma unroll 8
        for (int d = 0; d < HDq; d++) acc = fmaf(qi[d], kj[d], acc);
        int dy = i / 7 - j / 7 + 6;
        int dx = i % 7 - j % 7 + 6;
        ss[i * 50 + j] = acc * 0.125f + rel_bias[(dy * 13 + dx) * NHq + head];
    }
    __syncthreads();

    if (tid < NWq) {
        float* row = &ss[tid * 50];
        float m = -1e30f;
        for (int j = 0; j < NWq; j++) m = fmaxf(m, row[j]);
        float sum = 0.0f;
        for (int j = 0; j < NWq; j++) { float e = __expf(row[j] - m); row[j] = e; sum += e; }
        float r = 1.0f / sum;
        for (int j = 0; j < NWq; j++) row[j] *= r;
    }
    __syncthreads();

    for (int idx = tid; idx < NWq * HDq; idx += 128) {
        int i = idx >> 6, d = idx & 63;
        const float* pi = &ss[i * 50];
        float acc = 0.0f;
        #pragma unroll 7
        for (int j = 0; j < NWq; j++) acc = fmaf(pi[j], vs[j * 65 + d], acc);
        out[(size_t)growsh[i] * Cq + head * HDq + d] = __float2bfloat16(acc);
    }
}

// ---------------- depthwise 3x3 (NHWC, bf16 in/out) + bias + exact GELU ----
__global__ __launch_bounds__(256) void dwconv_gelu_kernel(
    const bf16* __restrict__ h1, const float* __restrict__ w,
    const float* __restrict__ bias, bf16* __restrict__ h2)
{
    int idx = blockIdx.x * 256 + threadIdx.x;     // (pixel, c8) pairs
    int c8  = idx % (HIDq / 8);
    int pix = idx / (HIDq / 8);
    int xq = pix % Wq;
    int yq = (pix / Wq) % Hq;
    int bq = pix / Ntok;
    int c = c8 * 8;

    float acc[8];
    #pragma unroll
    for (int i = 0; i < 8; i++) acc[i] = bias[c + i];

    #pragma unroll
    for (int dy = -1; dy <= 1; dy++) {
        int yy = yq + dy;
        if (yy < 0 || yy >= Hq) continue;
        #pragma unroll
        for (int dx = -1; dx <= 1; dx++) {
            int xx = xq + dx;
            if (xx < 0 || xx >= Wq) continue;
            size_t src = ((size_t)(bq * Ntok + yy * Wq + xx)) * HIDq + c;
            uint4 raw = *(const uint4*)(h1 + src);
            const bf16* pv = (const bf16*)&raw;
            int wk = (dy + 1) * 3 + (dx + 1);
            #pragma unroll
            for (int i = 0; i < 8; i++)
                acc[i] = fmaf(__bfloat162float(pv[i]), w[(c + i) * 9 + wk], acc[i]);
        }
    }
    const float is2 = 0.70710678118654752f;
    uint4 outraw;
    bf16* po = (bf16*)&outraw;
    #pragma unroll
    for (int i = 0; i < 8; i++) {
        float v = 0.5f * acc[i] * (1.0f + erff(acc[i] * is2));
        po[i] = __float2bfloat16(v);
    }
    *(uint4*)(h2 + (size_t)pix * HIDq + c) = outraw;
}

// ---------------- launch ----------------------------------------------------
extern "C" void kernel_launch(void* const* d_in, const int* in_sizes, int n_in,
                              void* d_out, int out_size)
{
    const float* x        = (const float*)d_in[0];
    const float* gamma1   = (const float*)d_in[1];
    const float* beta1    = (const float*)d_in[2];
    const float* w_qkv    = (const float*)d_in[3];
    const float* w_proj   = (const float*)d_in[4];
    const float* b_proj   = (const float*)d_in[5];
    const float* rel_bias = (const float*)d_in[6];
    const float* gamma2   = (const float*)d_in[7];
    const float* beta2    = (const float*)d_in[8];
    const float* w_fc1    = (const float*)d_in[9];
    const float* b_fc1    = (const float*)d_in[10];
    const float* w_dw     = (const float*)d_in[11];
    const float* b_dw     = (const float*)d_in[12];
    const float* w_fc2    = (const float*)d_in[13];
    const float* b_fc2    = (const float*)d_in[14];
    float* out = (float*)d_out;

    bf16 *xn, *qkv, *attnout, *h1, *h2, *wqkv, *wproj, *wfc1, *wfc2;
    cudaGetSymbolAddress((void**)&xn,      g_xn);
    cudaGetSymbolAddress((void**)&qkv,     g_qkv);
    cudaGetSymbolAddress((void**)&attnout, g_attnout);
    cudaGetSymbolAddress((void**)&h1,      g_h1);
    cudaGetSymbolAddress((void**)&h2,      g_h2);
    cudaGetSymbolAddress((void**)&wqkv,    g_wqkv);
    cudaGetSymbolAddress((void**)&wproj,   g_wproj);
    cudaGetSymbolAddress((void**)&wfc1,    g_wfc1);
    cudaGetSymbolAddress((void**)&wfc2,    g_wfc2);

    // 0. convert weights to bf16
    cvt_kernel<<<(Cq*3*Cq + 255)/256, 256>>>(w_qkv,  wqkv,  Cq*3*Cq);
    cvt_kernel<<<(Cq*Cq   + 255)/256, 256>>>(w_proj, wproj, Cq*Cq);
    cvt_kernel<<<(Cq*HIDq + 255)/256, 256>>>(w_fc1,  wfc1,  Cq*HIDq);
    cvt_kernel<<<(HIDq*Cq + 255)/256, 256>>>(w_fc2,  wfc2,  HIDq*Cq);

    // 1. LN1 -> bf16
    ln_kernel<<<ROWS, 128>>>(x, gamma1, beta1, xn);

    // 2. QKV gemm: (100352,384)@(384,1152) -> bf16
    {
        dim3 grid((3 * Cq) / 128, ROWS / 128);
        bf16_gemm_kernel<bf16, false, false><<<grid, 256>>>(xn, wqkv, nullptr, nullptr,
                                                            qkv, ROWS, 3 * Cq, Cq);
    }

    // 3. window attention -> bf16
    {
        dim3 grid(Bq * 64, NHq);
        attn_kernel<<<grid, 128>>>(qkv, rel_bias, attnout);
    }

    // 4. proj + bias + residual(x) -> d_out (fp32)
    {
        dim3 grid(Cq / 128, ROWS / 128);
        bf16_gemm_kernel<float, true, true><<<grid, 256>>>(attnout, wproj, b_proj, x,
                                                           out, ROWS, Cq, Cq);
    }

    // 5. LN2 -> bf16
    ln_kernel<<<ROWS, 128>>>(out, gamma2, beta2, xn);

    // 6. fc1 + bias -> bf16
    {
        dim3 grid(HIDq / 128, ROWS / 128);
        bf16_gemm_kernel<bf16, true, false><<<grid, 256>>>(xn, wfc1, b_fc1, nullptr,
                                                           h1, ROWS, HIDq, Cq);
    }

    // 7. depthwise 3x3 + bias + GELU -> bf16
    {
        int total = ROWS * (HIDq / 8);
        dwconv_gelu_kernel<<<total / 256, 256>>>(h1, w_dw, b_dw, h2);
    }

    // 8. fc2 + bias + residual(d_out) -> d_out (fp32)
    {
        dim3 grid(Cq / 128, ROWS / 128);
        bf16_gemm_kernel<float, true, true><<<grid, 256>>>(h2, wfc2, b_fc2, out,
                                                           out, ROWS, Cq, HIDq);
    }
}

// round 9
// speedup vs baseline: 3.8491x; 1.3184x over previous
#include <cuda_runtime.h>
#include <cuda_bf16.h>
#include <math.h>
#include <stdint.h>

typedef __nv_bfloat16 bf16;

// ---------------- problem constants ----------------
#define Bq    32
#define Hq    56
#define Wq    56
#define Cq    384
#define NHq   6
#define HDq   64
#define NWq   49
#define HIDq  1536
#define Ntok  (Hq*Wq)     // 3136
#define ROWS  (Bq*Ntok)   // 100352
#define LN_EPS 1e-5f

// ---------------- scratch (device globals) ----------------
__device__ bf16 g_xn[(size_t)ROWS * Cq];
__device__ bf16 g_qkv[(size_t)ROWS * 3 * Cq];
__device__ bf16 g_attnout[(size_t)ROWS * Cq];
__device__ bf16 g_h1[(size_t)ROWS * HIDq];
__device__ bf16 g_h2[(size_t)ROWS * HIDq];
__device__ bf16 g_wqkv[Cq * 3 * Cq];
__device__ bf16 g_wproj[Cq * Cq];
__device__ bf16 g_wfc1[Cq * HIDq];
__device__ bf16 g_wfc2[HIDq * Cq];

// ---------------- small helpers ----------------
__device__ __forceinline__ uint32_t smem_cast(const void* p) {
    return (uint32_t)__cvta_generic_to_shared(p);
}
__device__ __forceinline__ void cp16(uint32_t s, const void* g) {
    asm volatile("cp.async.cg.shared.global [%0], [%1], 16;\n" :: "r"(s), "l"(g));
}
__device__ __forceinline__ void cp_commit() {
    asm volatile("cp.async.commit_group;\n");
}
template<int N> __device__ __forceinline__ void cp_wait() {
    asm volatile("cp.async.wait_group %0;\n" :: "n"(N));
}
__device__ __forceinline__ void ldsm4(uint32_t* r, uint32_t a) {
    asm volatile("ldmatrix.sync.aligned.m8n8.x4.shared.b16 {%0,%1,%2,%3}, [%4];"
        : "=r"(r[0]), "=r"(r[1]), "=r"(r[2]), "=r"(r[3]) : "r"(a));
}
__device__ __forceinline__ void ldsm4t(uint32_t* r, uint32_t a) {
    asm volatile("ldmatrix.sync.aligned.m8n8.x4.trans.shared.b16 {%0,%1,%2,%3}, [%4];"
        : "=r"(r[0]), "=r"(r[1]), "=r"(r[2]), "=r"(r[3]) : "r"(a));
}
__device__ __forceinline__ void mma_bf16(float* c, const uint32_t* a, uint32_t b0, uint32_t b1) {
    asm volatile(
        "mma.sync.aligned.m16n8k16.row.col.f32.bf16.bf16.f32 "
        "{%0,%1,%2,%3}, {%4,%5,%6,%7}, {%8,%9}, {%0,%1,%2,%3};\n"
        : "+f"(c[0]), "+f"(c[1]), "+f"(c[2]), "+f"(c[3])
        : "r"(a[0]), "r"(a[1]), "r"(a[2]), "r"(a[3]), "r"(b0), "r"(b1));
}
__device__ __forceinline__ uint32_t packbf(float a, float b) {
    __nv_bfloat162 v = __float22bfloat162_rn(make_float2(a, b));
    return *(uint32_t*)&v;
}

// ---------------- fp32 -> bf16 convert ----------------
__global__ __launch_bounds__(256) void cvt_kernel(const float* __restrict__ s,
                                                  bf16* __restrict__ d, int n) {
    int i = blockIdx.x * 256 + threadIdx.x;
    if (i < n) d[i] = __float2bfloat16(s[i]);
}

// ---------------- LayerNorm (fp32 in, bf16 out) ----------------
__global__ __launch_bounds__(128) void ln_kernel(
    const float* __restrict__ x, const float* __restrict__ gamma,
    const float* __restrict__ beta, bf16* __restrict__ y)
{
    int row = blockIdx.x;
    const float* xr = x + (size_t)row * Cq;
    bf16* yr = y + (size_t)row * Cq;
    int tid = threadIdx.x;

    float v0 = xr[tid], v1 = xr[tid + 128], v2 = xr[tid + 256];
    float s  = v0 + v1 + v2;
    float s2 = v0*v0 + v1*v1 + v2*v2;
    #pragma unroll
    for (int o = 16; o > 0; o >>= 1) {
        s  += __shfl_down_sync(0xffffffffu, s,  o);
        s2 += __shfl_down_sync(0xffffffffu, s2, o);
    }
    __shared__ float sh[8];
    int wid = tid >> 5, lid = tid & 31;
    if (lid == 0) { sh[wid] = s; sh[wid + 4] = s2; }
    __syncthreads();
    if (tid == 0) {
        float ts = sh[0]+sh[1]+sh[2]+sh[3];
        float ts2 = sh[4]+sh[5]+sh[6]+sh[7];
        float mu = ts * (1.0f / Cq);
        float var = ts2 * (1.0f / Cq) - mu * mu;
        sh[0] = mu;
        sh[1] = rsqrtf(var + LN_EPS);
    }
    __syncthreads();
    float mu = sh[0], inv = sh[1];
    yr[tid]       = __float2bfloat16((v0 - mu) * inv * gamma[tid]       + beta[tid]);
    yr[tid + 128] = __float2bfloat16((v1 - mu) * inv * gamma[tid + 128] + beta[tid + 128]);
    yr[tid + 256] = __float2bfloat16((v2 - mu) * inv * gamma[tid + 256] + beta[tid + 256]);
}

// ---------------- bf16 tensor-core GEMM -------------------------------------
// C = A(MxK) @ B(KxN) [+ bias] [+ res].  M%128==0, N%128==0, K%32==0.
// CTA 128x128x32, 128 threads (4 warps, 64x64 warp tiles), 3-stage cp.async,
// swizzled smem + ldmatrix, mma.m16n8k16.bf16.
template<typename OT, bool BIAS, bool RES>
__global__ __launch_bounds__(128, 2) void bf16_gemm_kernel(
    const bf16* __restrict__ A, const bf16* __restrict__ B,
    const float* __restrict__ bias, const float* __restrict__ res,
    OT* __restrict__ C, int M, int N, int K)
{
    // per stage: A 128x32 bf16 (8KB, 64B rows, swizzled), B 32x128 (8KB, 256B rows)
    __shared__ __align__(16) char smem[3 * 16384];
    uint32_t sbase = smem_cast(smem);

    int tid = threadIdx.x, lane = tid & 31, warp = tid >> 5;
    int warp_m = warp & 1, warp_n = warp >> 1;      // 2x2 warp grid, 64x64 tiles
    int bm = blockIdx.y * 128, bn = blockIdx.x * 128;

    // ---- global->smem assignments (cp.async, 16B chunks), 8 per thread ----
    const bf16* gA[4]; uint32_t sA[4];
    const bf16* gB[4]; uint32_t sB[4];
    {
        int ar = tid >> 2, ag = tid & 3;
        #pragma unroll
        for (int q = 0; q < 4; q++) {
            int row = ar + 32 * q;
            gA[q] = A + (size_t)(bm + row) * K + ag * 8;
            sA[q] = row * 64 + ((ag ^ ((row >> 1) & 3)) << 4);
        }
        int bk = tid >> 4, bn8 = tid & 15;
        #pragma unroll
        for (int q = 0; q < 4; q++) {
            int k = bk + 8 * q;
            gB[q] = B + (size_t)k * N + bn + bn8 * 8;
            sB[q] = 8192 + k * 256 + (((bn8 & 8) | ((bn8 & 7) ^ (k & 7))) << 4);
        }
    }

    // ---- ldmatrix per-lane offsets ----
    int l7 = lane & 7, lb = (lane >> 3) & 1, lh = (lane >> 4) & 1;
    int arow = warp_m * 64 + l7 + lb * 8;
    uint32_t aoff[2];
    #pragma unroll
    for (int s = 0; s < 2; s++) {
        int gg = s * 2 + lh;
        aoff[s] = arow * 64 + ((gg ^ ((arow >> 1) & 3)) << 4);
    }
    int bkl = l7 + lb * 8;
    uint32_t boff[4];
    #pragma unroll
    for (int p = 0; p < 4; p++) {
        int n8 = warp_n * 8 + p * 2 + lh;
        boff[p] = 8192 + bkl * 256 + (((n8 & 8) | ((n8 & 7) ^ (bkl & 7))) << 4);
    }

    float acc[4][8][4];
    #pragma unroll
    for (int i = 0; i < 4; i++)
        #pragma unroll
        for (int j = 0; j < 8; j++)
            #pragma unroll
            for (int r = 0; r < 4; r++) acc[i][j][r] = 0.0f;

    int T = K / 32;
    auto issue = [&](int t, int st) {
        uint32_t sb = sbase + st * 16384;
        #pragma unroll
        for (int q = 0; q < 4; q++) cp16(sb + sA[q], gA[q] + t * 32);
        #pragma unroll
        for (int q = 0; q < 4; q++) cp16(sb + sB[q], gB[q] + (size_t)t * 32 * N);
    };

    issue(0, 0); cp_commit();
    issue(1, 1); cp_commit();
    cp_wait<1>(); __syncthreads();

    for (int t = 0; t < T; t++) {
        int st = t - (t / 3) * 3;
        if (t + 2 < T) issue(t + 2, (t + 2) % 3);
        cp_commit();

        uint32_t sb = sbase + st * 16384;
        #pragma unroll
        for (int s = 0; s < 2; s++) {
            uint32_t a[4][4], b[4][4];
            #pragma unroll
            for (int mi = 0; mi < 4; mi++) ldsm4(a[mi], sb + aoff[s] + mi * 1024);
            #pragma unroll
            for (int p = 0; p < 4; p++) ldsm4t(b[p], sb + boff[p] + s * 4096);
            #pragma unroll
            for (int mi = 0; mi < 4; mi++)
                #pragma unroll
                for (int p = 0; p < 4; p++) {
                    mma_bf16(acc[mi][2*p],   a[mi], b[p][0], b[p][1]);
                    mma_bf16(acc[mi][2*p+1], a[mi], b[p][2], b[p][3]);
                }
        }
        cp_wait<1>(); __syncthreads();
    }

    // ---- epilogue ----
    int g = lane >> 2, tig = lane & 3;
    #pragma unroll
    for (int mi = 0; mi < 4; mi++) {
        int row0 = bm + warp_m * 64 + mi * 16 + g;
        #pragma unroll
        for (int ni = 0; ni < 8; ni++) {
            int col = bn + warp_n * 64 + ni * 8 + tig * 2;
            size_t off0 = (size_t)row0 * N + col;
            size_t off1 = off0 + (size_t)8 * N;
            float c0 = acc[mi][ni][0], c1 = acc[mi][ni][1];
            float c2 = acc[mi][ni][2], c3 = acc[mi][ni][3];
            if (BIAS) {
                float b0 = bias[col], b1 = bias[col + 1];
                c0 += b0; c1 += b1; c2 += b0; c3 += b1;
            }
            if (RES) {
                float2 r0 = *(const float2*)(res + off0);
                float2 r1 = *(const float2*)(res + off1);
                c0 += r0.x; c1 += r0.y; c2 += r1.x; c3 += r1.y;
            }
            if constexpr (sizeof(OT) == 4) {
                *(float2*)((float*)C + off0) = make_float2(c0, c1);
                *(float2*)((float*)C + off1) = make_float2(c2, c3);
            } else {
                *(uint32_t*)((bf16*)C + off0) = packbf(c0, c1);
                *(uint32_t*)((bf16*)C + off1) = packbf(c2, c3);
            }
        }
    }
}

// ---------------- window attention via tensor cores -------------------------
// one block per (window, head); 128 threads = 4 warps; seq padded 49->64.
// Q/K/V in smem with 144B row stride (conflict-free ldmatrix, no swizzle).
__global__ __launch_bounds__(128) void attn_mma_kernel(
    const bf16* __restrict__ qkv, const float* __restrict__ rel_bias,
    bf16* __restrict__ out)
{
    __shared__ __align__(16) bf16 qs[64 * 72];
    __shared__ __align__(16) bf16 ks[64 * 72];
    __shared__ __align__(16) bf16 vs[64 * 72];
    __shared__ float bias_s[64 * 66];
    __shared__ int grow[NWq];

    int win = blockIdx.x, head = blockIdx.y;
    int b = win >> 6, wi = win & 63, wy = wi >> 3, wx = wi & 7;
    int tid = threadIdx.x, lane = tid & 31, warp = tid >> 5;

    if (tid < NWq) {
        int py = tid / 7, px = tid % 7;
        grow[tid] = b * Ntok + (wy * 7 + py) * Wq + (wx * 7 + px);
    }
    // zero pad rows 48..63 (row 48 overwritten below)
    for (int i = tid; i < 16 * 8 * 3; i += 128) {
        int arr = i >> 7;
        int rem = i & 127;
        int r = 48 + (rem >> 3), c8 = rem & 7;
        bf16* base = arr == 0 ? qs : (arr == 1 ? ks : vs);
        *(uint4*)&base[r * 72 + c8 * 8] = make_uint4(0, 0, 0, 0);
    }
    __syncthreads();

    for (int i = tid; i < NWq * 8; i += 128) {
        int r = i >> 3, c8 = i & 7;
        size_t gb = (size_t)grow[r] * (3 * Cq) + head * HDq + c8 * 8;
        *(uint4*)&qs[r * 72 + c8 * 8] = *(const uint4*)&qkv[gb];
        *(uint4*)&ks[r * 72 + c8 * 8] = *(const uint4*)&qkv[gb + Cq];
        *(uint4*)&vs[r * 72 + c8 * 8] = *(const uint4*)&qkv[gb + 2 * Cq];
    }
    for (int i = tid; i < 64 * 64; i += 128) {
        int ii = i >> 6, jj = i & 63;
        float v;
        if (jj >= NWq)      v = -1e30f;
        else if (ii >= NWq) v = 0.0f;
        else {
            int dy = ii / 7 - jj / 7 + 6;
            int dx = ii % 7 - jj % 7 + 6;
            v = rel_bias[(dy * 13 + dx) * NHq + head];
        }
        bias_s[ii * 66 + jj] = v;
    }
    __syncthreads();

    int g = lane >> 2, tig = lane & 3, l7 = lane & 7;
    int i0 = warp * 16;
    uint32_t qbase = smem_cast(qs), kbase = smem_cast(ks), vbase = smem_cast(vs);

    // ---- S = Q K^T ----
    float sc[8][4];
    #pragma unroll
    for (int n = 0; n < 8; n++)
        #pragma unroll
        for (int r = 0; r < 4; r++) sc[n][r] = 0.0f;

    #pragma unroll
    for (int t = 0; t < 4; t++) {
        uint32_t aq[4];
        uint32_t aaddr = qbase + (uint32_t)((i0 + (lane & 15)) * 144 + (t * 16 + ((lane >> 4) << 3)) * 2);
        ldsm4(aq, aaddr);
        #pragma unroll
        for (int p = 0; p < 4; p++) {
            uint32_t bk[4];
            int m = lane >> 3;
            int nrow = (p * 2 + (m >> 1)) * 8 + l7;
            uint32_t baddr = kbase + (uint32_t)(nrow * 144 + (t * 16 + ((m & 1) << 3)) * 2);
            ldsm4(bk, baddr);
            mma_bf16(sc[p * 2],     aq, bk[0], bk[1]);
            mma_bf16(sc[p * 2 + 1], aq, bk[2], bk[3]);
        }
    }

    // ---- scale + bias + softmax (rows i0+g and i0+g+8) ----
    float m0 = -1e30f, m1 = -1e30f;
    #pragma unroll
    for (int n = 0; n < 8; n++) {
        int j = n * 8 + tig * 2;
        float2 b0 = *(float2*)&bias_s[(i0 + g) * 66 + j];
        float2 b1 = *(float2*)&bias_s[(i0 + g + 8) * 66 + j];
        sc[n][0] = fmaf(sc[n][0], 0.125f, b0.x);
        sc[n][1] = fmaf(sc[n][1], 0.125f, b0.y);
        sc[n][2] = fmaf(sc[n][2], 0.125f, b1.x);
        sc[n][3] = fmaf(sc[n][3], 0.125f, b1.y);
        m0 = fmaxf(m0, fmaxf(sc[n][0], sc[n][1]));
        m1 = fmaxf(m1, fmaxf(sc[n][2], sc[n][3]));
    }
    #pragma unroll
    for (int o = 1; o < 4; o <<= 1) {
        m0 = fmaxf(m0, __shfl_xor_sync(0xffffffffu, m0, o));
        m1 = fmaxf(m1, __shfl_xor_sync(0xffffffffu, m1, o));
    }
    float s0 = 0.0f, s1 = 0.0f;
    #pragma unroll
    for (int n = 0; n < 8; n++) {
        sc[n][0] = __expf(sc[n][0] - m0);
        sc[n][1] = __expf(sc[n][1] - m0);
        sc[n][2] = __expf(sc[n][2] - m1);
        sc[n][3] = __expf(sc[n][3] - m1);
        s0 += sc[n][0] + sc[n][1];
        s1 += sc[n][2] + sc[n][3];
    }
    #pragma unroll
    for (int o = 1; o < 4; o <<= 1) {
        s0 += __shfl_xor_sync(0xffffffffu, s0, o);
        s1 += __shfl_xor_sync(0xffffffffu, s1, o);
    }
    float inv0 = 1.0f / s0, inv1 = 1.0f / s1;

    // re-pack P fragments: C-frag of S == A-frag of P (k = j)
    uint32_t pa[4][4];
    #pragma unroll
    for (int t = 0; t < 4; t++) {
        pa[t][0] = packbf(sc[2 * t][0] * inv0,     sc[2 * t][1] * inv0);
        pa[t][1] = packbf(sc[2 * t][2] * inv1,     sc[2 * t][3] * inv1);
        pa[t][2] = packbf(sc[2 * t + 1][0] * inv0, sc[2 * t + 1][1] * inv0);
        pa[t][3] = packbf(sc[2 * t + 1][2] * inv1, sc[2 * t + 1][3] * inv1);
    }

    // ---- O = P V ----
    float oa[8][4];
    #pragma unroll
    for (int n = 0; n < 8; n++)
        #pragma unroll
        for (int r = 0; r < 4; r++) oa[n][r] = 0.0f;

    int lb = (lane >> 3) & 1, lh = (lane >> 4) & 1;
    #pragma unroll
    for (int t = 0; t < 4; t++) {
        #pragma unroll
        for (int p = 0; p < 4; p++) {
            uint32_t bv[4];
            uint32_t vaddr = vbase + (uint32_t)((t * 16 + l7 + lb * 8) * 144 + (p * 16 + lh * 8) * 2);
            ldsm4t(bv, vaddr);
            mma_bf16(oa[p * 2],     pa[t], bv[0], bv[1]);
            mma_bf16(oa[p * 2 + 1], pa[t], bv[2], bv[3]);
        }
    }

    // ---- scatter (window reverse) ----
    int iA = i0 + g, iB = iA + 8;
    bool wA = iA < NWq, wB = iB < NWq;
    #pragma unroll
    for (int n = 0; n < 8; n++) {
        int col = head * HDq + n * 8 + tig * 2;
        if (wA) *(uint32_t*)&out[(size_t)grow[iA] * Cq + col] = packbf(oa[n][0], oa[n][1]);
        if (wB) *(uint32_t*)&out[(size_t)grow[iB] * Cq + col] = packbf(oa[n][2], oa[n][3]);
    }
}

// ---------------- depthwise 3x3 (NHWC, bf16 in/out) + bias + exact GELU ----
__global__ __launch_bounds__(256) void dwconv_gelu_kernel(
    const bf16* __restrict__ h1, const float* __restrict__ w,
    const float* __restrict__ bias, bf16* __restrict__ h2)
{
    int idx = blockIdx.x * 256 + threadIdx.x;     // (pixel, c8) pairs
    int c8  = idx % (HIDq / 8);
    int pix = idx / (HIDq / 8);
    int xq = pix % Wq;
    int yq = (pix / Wq) % Hq;
    int bq = pix / Ntok;
    int c = c8 * 8;

    float acc[8];
    #pragma unroll
    for (int i = 0; i < 8; i++) acc[i] = bias[c + i];

    #pragma unroll
    for (int dy = -1; dy <= 1; dy++) {
        int yy = yq + dy;
        if (yy < 0 || yy >= Hq) continue;
        #pragma unroll
        for (int dx = -1; dx <= 1; dx++) {
            int xx = xq + dx;
            if (xx < 0 || xx >= Wq) continue;
            size_t src = ((size_t)(bq * Ntok + yy * Wq + xx)) * HIDq + c;
            uint4 raw = *(const uint4*)(h1 + src);
            const bf16* pv = (const bf16*)&raw;
            int wk = (dy + 1) * 3 + (dx + 1);
            #pragma unroll
            for (int i = 0; i < 8; i++)
                acc[i] = fmaf(__bfloat162float(pv[i]), w[(c + i) * 9 + wk], acc[i]);
        }
    }
    const float is2 = 0.70710678118654752f;
    uint4 outraw;
    bf16* po = (bf16*)&outraw;
    #pragma unroll
    for (int i = 0; i < 8; i++) {
        float v = 0.5f * acc[i] * (1.0f + erff(acc[i] * is2));
        po[i] = __float2bfloat16(v);
    }
    *(uint4*)(h2 + (size_t)pix * HIDq + c) = outraw;
}

// ---------------- launch ----------------------------------------------------
extern "C" void kernel_launch(void* const* d_in, const int* in_sizes, int n_in,
                              void* d_out, int out_size)
{
    const float* x        = (const float*)d_in[0];
    const float* gamma1   = (const float*)d_in[1];
    const float* beta1    = (const float*)d_in[2];
    const float* w_qkv    = (const float*)d_in[3];
    const float* w_proj   = (const float*)d_in[4];
    const float* b_proj   = (const float*)d_in[5];
    const float* rel_bias = (const float*)d_in[6];
    const float* gamma2   = (const float*)d_in[7];
    const float* beta2    = (const float*)d_in[8];
    const float* w_fc1    = (const float*)d_in[9];
    const float* b_fc1    = (const float*)d_in[10];
    const float* w_dw     = (const float*)d_in[11];
    const float* b_dw     = (const float*)d_in[12];
    const float* w_fc2    = (const float*)d_in[13];
    const float* b_fc2    = (const float*)d_in[14];
    float* out = (float*)d_out;

    bf16 *xn, *qkv, *attnout, *h1, *h2, *wqkv, *wproj, *wfc1, *wfc2;
    cudaGetSymbolAddress((void**)&xn,      g_xn);
    cudaGetSymbolAddress((void**)&qkv,     g_qkv);
    cudaGetSymbolAddress((void**)&attnout, g_attnout);
    cudaGetSymbolAddress((void**)&h1,      g_h1);
    cudaGetSymbolAddress((void**)&h2,      g_h2);
    cudaGetSymbolAddress((void**)&wqkv,    g_wqkv);
    cudaGetSymbolAddress((void**)&wproj,   g_wproj);
    cudaGetSymbolAddress((void**)&wfc1,    g_wfc1);
    cudaGetSymbolAddress((void**)&wfc2,    g_wfc2);

    // 0. convert weights to bf16
    cvt_kernel<<<(Cq*3*Cq + 255)/256, 256>>>(w_qkv,  wqkv,  Cq*3*Cq);
    cvt_kernel<<<(Cq*Cq   + 255)/256, 256>>>(w_proj, wproj, Cq*Cq);
    cvt_kernel<<<(Cq*HIDq + 255)/256, 256>>>(w_fc1,  wfc1,  Cq*HIDq);
    cvt_kernel<<<(HIDq*Cq + 255)/256, 256>>>(w_fc2,  wfc2,  HIDq*Cq);

    // 1. LN1 -> bf16
    ln_kernel<<<ROWS, 128>>>(x, gamma1, beta1, xn);

    // 2. QKV gemm -> bf16
    {
        dim3 grid((3 * Cq) / 128, ROWS / 128);
        bf16_gemm_kernel<bf16, false, false><<<grid, 128>>>(xn, wqkv, nullptr, nullptr,
                                                            qkv, ROWS, 3 * Cq, Cq);
    }

    // 3. window attention (tensor cores) -> bf16
    {
        dim3 grid(Bq * 64, NHq);
        attn_mma_kernel<<<grid, 128>>>(qkv, rel_bias, attnout);
    }

    // 4. proj + bias + residual(x) -> d_out (fp32)
    {
        dim3 grid(Cq / 128, ROWS / 128);
        bf16_gemm_kernel<float, true, true><<<grid, 128>>>(attnout, wproj, b_proj, x,
                                                           out, ROWS, Cq, Cq);
    }

    // 5. LN2 -> bf16
    ln_kernel<<<ROWS, 128>>>(out, gamma2, beta2, xn);

    // 6. fc1 + bias -> bf16
    {
        dim3 grid(HIDq / 128, ROWS / 128);
        bf16_gemm_kernel<bf16, true, false><<<grid, 128>>>(xn, wfc1, b_fc1, nullptr,
                                                           h1, ROWS, HIDq, Cq);
    }

    // 7. depthwise 3x3 + bias + GELU -> bf16
    {
        int total = ROWS * (HIDq / 8);
        dwconv_gelu_kernel<<<(total + 255) / 256, 256>>>(h1, w_dw, b_dw, h2);
    }

    // 8. fc2 + bias + residual(d_out) -> d_out (fp32)
    {
        dim3 grid(Cq / 128, ROWS / 128);
        bf16_gemm_kernel<float, true, true><<<grid, 128>>>(h2, wfc2, b_fc2, out,
                                                           out, ROWS, Cq, HIDq);
    }
}

// round 15
// speedup vs baseline: 3.8646x; 1.0040x over previous
#include <cuda_runtime.h>
#include <cuda_bf16.h>
#include <math.h>
#include <stdint.h>

typedef __nv_bfloat16 bf16;

// ---------------- problem constants ----------------
#define Bq    32
#define Hq    56
#define Wq    56
#define Cq    384
#define NHq   6
#define HDq   64
#define NWq   49
#define HIDq  1536
#define Ntok  (Hq*Wq)     // 3136
#define ROWS  (Bq*Ntok)   // 100352
#define LN_EPS 1e-5f

// ---------------- scratch (device globals) ----------------
__device__ bf16 g_xn[(size_t)ROWS * Cq];
__device__ bf16 g_qkv[(size_t)ROWS * 3 * Cq];
__device__ bf16 g_attnout[(size_t)ROWS * Cq];
__device__ bf16 g_h1[(size_t)ROWS * HIDq];
__device__ bf16 g_h2[(size_t)ROWS * HIDq];
__device__ bf16 g_wqkv[Cq * 3 * Cq];
__device__ bf16 g_wproj[Cq * Cq];
__device__ bf16 g_wfc1[Cq * HIDq];
__device__ bf16 g_wfc2[HIDq * Cq];
__device__ float g_biastbl[NHq * 64 * 66];

// ---------------- small helpers ----------------
__device__ __forceinline__ uint32_t smem_cast(const void* p) {
    return (uint32_t)__cvta_generic_to_shared(p);
}
__device__ __forceinline__ void cp16(uint32_t s, const void* g) {
    asm volatile("cp.async.cg.shared.global [%0], [%1], 16;\n" :: "r"(s), "l"(g));
}
__device__ __forceinline__ void cp_commit() {
    asm volatile("cp.async.commit_group;\n");
}
template<int N> __device__ __forceinline__ void cp_wait() {
    asm volatile("cp.async.wait_group %0;\n" :: "n"(N));
}
__device__ __forceinline__ void ldsm4(uint32_t* r, uint32_t a) {
    asm volatile("ldmatrix.sync.aligned.m8n8.x4.shared.b16 {%0,%1,%2,%3}, [%4];"
        : "=r"(r[0]), "=r"(r[1]), "=r"(r[2]), "=r"(r[3]) : "r"(a));
}
__device__ __forceinline__ void ldsm4t(uint32_t* r, uint32_t a) {
    asm volatile("ldmatrix.sync.aligned.m8n8.x4.trans.shared.b16 {%0,%1,%2,%3}, [%4];"
        : "=r"(r[0]), "=r"(r[1]), "=r"(r[2]), "=r"(r[3]) : "r"(a));
}
__device__ __forceinline__ void mma_bf16(float* c, const uint32_t* a, uint32_t b0, uint32_t b1) {
    asm volatile(
        "mma.sync.aligned.m16n8k16.row.col.f32.bf16.bf16.f32 "
        "{%0,%1,%2,%3}, {%4,%5,%6,%7}, {%8,%9}, {%0,%1,%2,%3};\n"
        : "+f"(c[0]), "+f"(c[1]), "+f"(c[2]), "+f"(c[3])
        : "r"(a[0]), "r"(a[1]), "r"(a[2]), "r"(a[3]), "r"(b0), "r"(b1));
}
__device__ __forceinline__ uint32_t packbf(float a, float b) {
    __nv_bfloat162 v = __float22bfloat162_rn(make_float2(a, b));
    return *(uint32_t*)&v;
}

// ---------------- fp32 -> bf16 convert ----------------
__global__ __launch_bounds__(256) void cvt_kernel(const float* __restrict__ s,
                                                  bf16* __restrict__ d, int n) {
    int i = blockIdx.x * 256 + threadIdx.x;
    if (i < n) d[i] = __float2bfloat16(s[i]);
}

// ---------------- attention bias table: tbl[head][i*66+j] ----------------
__global__ __launch_bounds__(64) void bias_table_kernel(
    const float* __restrict__ rel_bias, float* __restrict__ tbl)
{
    int head = blockIdx.y, i = blockIdx.x, j = threadIdx.x;
    float v;
    if (j >= NWq)      v = -1e30f;
    else if (i >= NWq) v = 0.0f;
    else {
        int dy = i / 7 - j / 7 + 6;
        int dx = i % 7 - j % 7 + 6;
        v = rel_bias[(dy * 13 + dx) * NHq + head];
    }
    tbl[head * (64 * 66) + i * 66 + j] = v;
}

// ---------------- LayerNorm (fp32 in, bf16 out) ----------------
__global__ __launch_bounds__(128) void ln_kernel(
    const float* __restrict__ x, const float* __restrict__ gamma,
    const float* __restrict__ beta, bf16* __restrict__ y)
{
    int row = blockIdx.x;
    const float* xr = x + (size_t)row * Cq;
    bf16* yr = y + (size_t)row * Cq;
    int tid = threadIdx.x;

    float v0 = xr[tid], v1 = xr[tid + 128], v2 = xr[tid + 256];
    float s  = v0 + v1 + v2;
    float s2 = v0*v0 + v1*v1 + v2*v2;
    #pragma unroll
    for (int o = 16; o > 0; o >>= 1) {
        s  += __shfl_down_sync(0xffffffffu, s,  o);
        s2 += __shfl_down_sync(0xffffffffu, s2, o);
    }
    __shared__ float sh[8];
    int wid = tid >> 5, lid = tid & 31;
    if (lid == 0) { sh[wid] = s; sh[wid + 4] = s2; }
    __syncthreads();
    if (tid == 0) {
        float ts = sh[0]+sh[1]+sh[2]+sh[3];
        float ts2 = sh[4]+sh[5]+sh[6]+sh[7];
        float mu = ts * (1.0f / Cq);
        float var = ts2 * (1.0f / Cq) - mu * mu;
        sh[0] = mu;
        sh[1] = rsqrtf(var + LN_EPS);
    }
    __syncthreads();
    float mu = sh[0], inv = sh[1];
    yr[tid]       = __float2bfloat16((v0 - mu) * inv * gamma[tid]       + beta[tid]);
    yr[tid + 128] = __float2bfloat16((v1 - mu) * inv * gamma[tid + 128] + beta[tid + 128]);
    yr[tid + 256] = __float2bfloat16((v2 - mu) * inv * gamma[tid + 256] + beta[tid + 256]);
}

// ---------------- bf16 tensor-core GEMM -------------------------------------
// C = A(MxK) @ B(KxN) [+ bias] [+ res].  M%128==0, N%128==0, K%32==0.
// CTA 128x128x32, 256 threads = 8 warps in 4(M)x2(N) grid, 32x64 warp tiles
// (4 warps/SMSP at 2 CTAs/SM), 3-stage cp.async, swizzled smem + ldmatrix.
template<typename OT, bool BIAS, bool RES>
__global__ __launch_bounds__(256, 2) void bf16_gemm_kernel(
    const bf16* __restrict__ A, const bf16* __restrict__ B,
    const float* __restrict__ bias, const float* __restrict__ res,
    OT* __restrict__ C, int M, int N, int K)
{
    // per stage: A 128x32 bf16 (8KB, 64B rows, swizzled) then B 32x128 (8KB, 256B rows)
    __shared__ __align__(16) char smem[3 * 16384];
    uint32_t sbase = smem_cast(smem);

    int tid = threadIdx.x, lane = tid & 31, warp = tid >> 5;
    int warp_m = warp & 3, warp_n = warp >> 2;   // 4x2 warp grid, 32x64 tiles
    int bm = blockIdx.y * 128, bn = blockIdx.x * 128;

    // ---- global->smem assignments (cp.async, 16B chunks) — R5-validated ----
    int arow0 = tid >> 2;            // 0..63
    int ag    = tid & 3;             // k-group (8 bf16 each)
    const bf16* gA0 = A + (size_t)(bm + arow0) * K + ag * 8;
    const bf16* gA1 = gA0 + (size_t)64 * K;
    uint32_t sA0 = arow0 * 64 + ((ag ^ ((arow0 >> 1) & 3)) << 4);
    int arow1 = arow0 + 64;
    uint32_t sA1 = arow1 * 64 + ((ag ^ ((arow1 >> 1) & 3)) << 4);

    int bk0 = tid >> 4;              // 0..15
    int bn8 = tid & 15;              // n-group (8 bf16 each)
    const bf16* gB0 = B + (size_t)bk0 * N + bn + bn8 * 8;
    const bf16* gB1 = gB0 + (size_t)16 * N;
    uint32_t sB0 = 8192 + bk0 * 256 + (((bn8 & 8) | ((bn8 & 7) ^ (bk0 & 7))) << 4);
    int bk1 = bk0 + 16;
    uint32_t sB1 = 8192 + bk1 * 256 + (((bn8 & 8) | ((bn8 & 7) ^ (bk1 & 7))) << 4);

    // ---- ldmatrix per-lane offsets ----
    int l7 = lane & 7, lb = (lane >> 3) & 1, lh = (lane >> 4) & 1;
    int arow = warp_m * 32 + l7 + lb * 8;            // mi adds 16 rows = +1024B
    uint32_t aoff[2];
    #pragma unroll
    for (int s = 0; s < 2; s++) {
        int gg = s * 2 + lh;
        aoff[s] = arow * 64 + ((gg ^ ((arow >> 1) & 3)) << 4);
    }
    int bkl = l7 + lb * 8;                           // k within k16; s adds 4096B
    uint32_t boff[4];
    #pragma unroll
    for (int p = 0; p < 4; p++) {
        int n8 = warp_n * 8 + p * 2 + lh;
        boff[p] = 8192 + bkl * 256 + (((n8 & 8) | ((n8 & 7) ^ (bkl & 7))) << 4);
    }

    float acc[2][8][4];
    #pragma unroll
    for (int i = 0; i < 2; i++)
        #pragma unroll
        for (int j = 0; j < 8; j++)
            #pragma unroll
            for (int r = 0; r < 4; r++) acc[i][j][r] = 0.0f;

    int T = K / 32;
    auto issue = [&](int t, int st) {
        uint32_t sb = sbase + st * 16384;
        cp16(sb + sA0, gA0 + t * 32);
        cp16(sb + sA1, gA1 + t * 32);
        cp16(sb + sB0, gB0 + (size_t)t * 32 * N);
        cp16(sb + sB1, gB1 + (size_t)t * 32 * N);
    };

    issue(0, 0); cp_commit();
    issue(1, 1); cp_commit();
    cp_wait<1>(); __syncthreads();

    for (int t = 0; t < T; t++) {
        int st = t - (t / 3) * 3;
        if (t + 2 < T) issue(t + 2, (t + 2) % 3);
        cp_commit();

        uint32_t sb = sbase + st * 16384;
        #pragma unroll
        for (int s = 0; s < 2; s++) {
            uint32_t a[2][4], b[4][4];
            #pragma unroll
            for (int mi = 0; mi < 2; mi++) ldsm4(a[mi], sb + aoff[s] + mi * 1024);
            #pragma unroll
            for (int p = 0; p < 4; p++) ldsm4t(b[p], sb + boff[p] + s * 4096);
            #pragma unroll
            for (int mi = 0; mi < 2; mi++)
                #pragma unroll
                for (int p = 0; p < 4; p++) {
                    mma_bf16(acc[mi][2*p],   a[mi], b[p][0], b[p][1]);
                    mma_bf16(acc[mi][2*p+1], a[mi], b[p][2], b[p][3]);
                }
        }
        cp_wait<1>(); __syncthreads();
    }

    // ---- epilogue ----
    int g = lane >> 2, tig = lane & 3;
    #pragma unroll
    for (int mi = 0; mi < 2; mi++) {
        int row0 = bm + warp_m * 32 + mi * 16 + g;
        #pragma unroll
        for (int ni = 0; ni < 8; ni++) {
            int col = bn + warp_n * 64 + ni * 8 + tig * 2;
            size_t off0 = (size_t)row0 * N + col;
            size_t off1 = off0 + (size_t)8 * N;
            float c0 = acc[mi][ni][0], c1 = acc[mi][ni][1];
            float c2 = acc[mi][ni][2], c3 = acc[mi][ni][3];
            if (BIAS) {
                float b0 = bias[col], b1 = bias[col + 1];
                c0 += b0; c1 += b1; c2 += b0; c3 += b1;
            }
            if (RES) {
                float2 r0 = *(const float2*)(res + off0);
                float2 r1 = *(const float2*)(res + off1);
                c0 += r0.x; c1 += r0.y; c2 += r1.x; c3 += r1.y;
            }
            if constexpr (sizeof(OT) == 4) {
                *(float2*)((float*)C + off0) = make_float2(c0, c1);
                *(float2*)((float*)C + off1) = make_float2(c2, c3);
            } else {
                *(uint32_t*)((bf16*)C + off0) = packbf(c0, c1);
                *(uint32_t*)((bf16*)C + off1) = packbf(c2, c3);
            }
        }
    }
}

// ---------------- window attention via tensor cores -------------------------
__global__ __launch_bounds__(128) void attn_mma_kernel(
    const bf16* __restrict__ qkv, const float* __restrict__ biastbl,
    bf16* __restrict__ out)
{
    __shared__ __align__(16) bf16 qs[64 * 72];
    __shared__ __align__(16) bf16 ks[64 * 72];
    __shared__ __align__(16) bf16 vs[64 * 72];
    __shared__ int grow[NWq];

    int win = blockIdx.x, head = blockIdx.y;
    int b = win >> 6, wi = win & 63, wy = wi >> 3, wx = wi & 7;
    int tid = threadIdx.x, lane = tid & 31, warp = tid >> 5;

    if (tid < NWq) {
        int py = tid / 7, px = tid % 7;
        grow[tid] = b * Ntok + (wy * 7 + py) * Wq + (wx * 7 + px);
    }
    for (int i = tid; i < 16 * 8 * 3; i += 128) {
        int arr = i >> 7;
        int rem = i & 127;
        int r = 48 + (rem >> 3), c8 = rem & 7;
        bf16* base = arr == 0 ? qs : (arr == 1 ? ks : vs);
        *(uint4*)&base[r * 72 + c8 * 8] = make_uint4(0, 0, 0, 0);
    }
    __syncthreads();

    for (int i = tid; i < NWq * 8; i += 128) {
        int r = i >> 3, c8 = i & 7;
        size_t gb = (size_t)grow[r] * (3 * Cq) + head * HDq + c8 * 8;
        *(uint4*)&qs[r * 72 + c8 * 8] = *(const uint4*)&qkv[gb];
        *(uint4*)&ks[r * 72 + c8 * 8] = *(const uint4*)&qkv[gb + Cq];
        *(uint4*)&vs[r * 72 + c8 * 8] = *(const uint4*)&qkv[gb + 2 * Cq];
    }
    __syncthreads();

    int g = lane >> 2, tig = lane & 3, l7 = lane & 7;
    int i0 = warp * 16;
    uint32_t qbase = smem_cast(qs), kbase = smem_cast(ks), vbase = smem_cast(vs);
    const float* bt = biastbl + head * (64 * 66);

    float sc[8][4];
    #pragma unroll
    for (int n = 0; n < 8; n++)
        #pragma unroll
        for (int r = 0; r < 4; r++) sc[n][r] = 0.0f;

    #pragma unroll
    for (int t = 0; t < 4; t++) {
        uint32_t aq[4];
        uint32_t aaddr = qbase + (uint32_t)((i0 + (lane & 15)) * 144 + (t * 16 + ((lane >> 4) << 3)) * 2);
        ldsm4(aq, aaddr);
        #pragma unroll
        for (int p = 0; p < 4; p++) {
            uint32_t bk[4];
            int m = lane >> 3;
            int nrow = (p * 2 + (m >> 1)) * 8 + l7;
            uint32_t baddr = kbase + (uint32_t)(nrow * 144 + (t * 16 + ((m & 1) << 3)) * 2);
            ldsm4(bk, baddr);
            mma_bf16(sc[p * 2],     aq, bk[0], bk[1]);
            mma_bf16(sc[p * 2 + 1], aq, bk[2], bk[3]);
        }
    }

    float m0 = -1e30f, m1 = -1e30f;
    #pragma unroll
    for (int n = 0; n < 8; n++) {
        int j = n * 8 + tig * 2;
        float2 b0 = *(const float2*)&bt[(i0 + g) * 66 + j];
        float2 b1 = *(const float2*)&bt[(i0 + g + 8) * 66 + j];
        sc[n][0] = fmaf(sc[n][0], 0.125f, b0.x);
        sc[n][1] = fmaf(sc[n][1], 0.125f, b0.y);
        sc[n][2] = fmaf(sc[n][2], 0.125f, b1.x);
        sc[n][3] = fmaf(sc[n][3], 0.125f, b1.y);
        m0 = fmaxf(m0, fmaxf(sc[n][0], sc[n][1]));
        m1 = fmaxf(m1, fmaxf(sc[n][2], sc[n][3]));
    }
    #pragma unroll
    for (int o = 1; o < 4; o <<= 1) {
        m0 = fmaxf(m0, __shfl_xor_sync(0xffffffffu, m0, o));
        m1 = fmaxf(m1, __shfl_xor_sync(0xffffffffu, m1, o));
    }
    float s0 = 0.0f, s1 = 0.0f;
    #pragma unroll
    for (int n = 0; n < 8; n++) {
        sc[n][0] = __expf(sc[n][0] - m0);
        sc[n][1] = __expf(sc[n][1] - m0);
        sc[n][2] = __expf(sc[n][2] - m1);
        sc[n][3] = __expf(sc[n][3] - m1);
        s0 += sc[n][0] + sc[n][1];
        s1 += sc[n][2] + sc[n][3];
    }
    #pragma unroll
    for (int o = 1; o < 4; o <<= 1) {
        s0 += __shfl_xor_sync(0xffffffffu, s0, o);
        s1 += __shfl_xor_sync(0xffffffffu, s1, o);
    }
    float inv0 = 1.0f / s0, inv1 = 1.0f / s1;

    uint32_t pa[4][4];
    #pragma unroll
    for (int t = 0; t < 4; t++) {
        pa[t][0] = packbf(sc[2 * t][0] * inv0,     sc[2 * t][1] * inv0);
        pa[t][1] = packbf(sc[2 * t][2] * inv1,     sc[2 * t][3] * inv1);
        pa[t][2] = packbf(sc[2 * t + 1][0] * inv0, sc[2 * t + 1][1] * inv0);
        pa[t][3] = packbf(sc[2 * t + 1][2] * inv1, sc[2 * t + 1][3] * inv1);
    }

    float oa[8][4];
    #pragma unroll
    for (int n = 0; n < 8; n++)
        #pragma unroll
        for (int r = 0; r < 4; r++) oa[n][r] = 0.0f;

    int lb = (lane >> 3) & 1, lh = (lane >> 4) & 1;
    #pragma unroll
    for (int t = 0; t < 4; t++) {
        #pragma unroll
        for (int p = 0; p < 4; p++) {
            uint32_t bv[4];
            uint32_t vaddr = vbase + (uint32_t)((t * 16 + l7 + lb * 8) * 144 + (p * 16 + lh * 8) * 2);
            ldsm4t(bv, vaddr);
            mma_bf16(oa[p * 2],     pa[t], bv[0], bv[1]);
            mma_bf16(oa[p * 2 + 1], pa[t], bv[2], bv[3]);
        }
    }

    int iA = i0 + g, iB = iA + 8;
    bool wA = iA < NWq, wB = iB < NWq;
    #pragma unroll
    for (int n = 0; n < 8; n++) {
        int col = head * HDq + n * 8 + tig * 2;
        if (wA) *(uint32_t*)&out[(size_t)grow[iA] * Cq + col] = packbf(oa[n][0], oa[n][1]);
        if (wB) *(uint32_t*)&out[(size_t)grow[iB] * Cq + col] = packbf(oa[n][2], oa[n][3]);
    }
}

// ---------------- depthwise 3x3 (NHWC, bf16 in/out) + bias + exact GELU ----
__global__ __launch_bounds__(256) void dwconv_gelu_kernel(
    const bf16* __restrict__ h1, const float* __restrict__ w,
    const float* __restrict__ bias, bf16* __restrict__ h2)
{
    int idx = blockIdx.x * 256 + threadIdx.x;     // (pixel, c8) pairs
    int c8  = idx % (HIDq / 8);
    int pix = idx / (HIDq / 8);
    int xq = pix % Wq;
    int yq = (pix / Wq) % Hq;
    int bq = pix / Ntok;
    int c = c8 * 8;

    float acc[8];
    #pragma unroll
    for (int i = 0; i < 8; i++) acc[i] = bias[c + i];

    #pragma unroll
    for (int dy = -1; dy <= 1; dy++) {
        int yy = yq + dy;
        if (yy < 0 || yy >= Hq) continue;
        #pragma unroll
        for (int dx = -1; dx <= 1; dx++) {
            int xx = xq + dx;
            if (xx < 0 || xx >= Wq) continue;
            size_t src = ((size_t)(bq * Ntok + yy * Wq + xx)) * HIDq + c;
            uint4 raw = *(const uint4*)(h1 + src);
            const bf16* pv = (const bf16*)&raw;
            int wk = (dy + 1) * 3 + (dx + 1);
            #pragma unroll
            for (int i = 0; i < 8; i++)
                acc[i] = fmaf(__bfloat162float(pv[i]), w[(c + i) * 9 + wk], acc[i]);
        }
    }
    const float is2 = 0.70710678118654752f;
    uint4 outraw;
    bf16* po = (bf16*)&outraw;
    #pragma unroll
    for (int i = 0; i < 8; i++) {
        float v = 0.5f * acc[i] * (1.0f + erff(acc[i] * is2));
        po[i] = __float2bfloat16(v);
    }
    *(uint4*)(h2 + (size_t)pix * HIDq + c) = outraw;
}

// ---------------- launch ----------------------------------------------------
extern "C" void kernel_launch(void* const* d_in, const int* in_sizes, int n_in,
                              void* d_out, int out_size)
{
    const float* x        = (const float*)d_in[0];
    const float* gamma1   = (const float*)d_in[1];
    const float* beta1    = (const float*)d_in[2];
    const float* w_qkv    = (const float*)d_in[3];
    const float* w_proj   = (const float*)d_in[4];
    const float* b_proj   = (const float*)d_in[5];
    const float* rel_bias = (const float*)d_in[6];
    const float* gamma2   = (const float*)d_in[7];
    const float* beta2    = (const float*)d_in[8];
    const float* w_fc1    = (const float*)d_in[9];
    const float* b_fc1    = (const float*)d_in[10];
    const float* w_dw     = (const float*)d_in[11];
    const float* b_dw     = (const float*)d_in[12];
    const float* w_fc2    = (const float*)d_in[13];
    const float* b_fc2    = (const float*)d_in[14];
    float* out = (float*)d_out;

    bf16 *xn, *qkv, *attnout, *h1, *h2, *wqkv, *wproj, *wfc1, *wfc2;
    float* btbl;
    cudaGetSymbolAddress((void**)&xn,      g_xn);
    cudaGetSymbolAddress((void**)&qkv,     g_qkv);
    cudaGetSymbolAddress((void**)&attnout, g_attnout);
    cudaGetSymbolAddress((void**)&h1,      g_h1);
    cudaGetSymbolAddress((void**)&h2,      g_h2);
    cudaGetSymbolAddress((void**)&wqkv,    g_wqkv);
    cudaGetSymbolAddress((void**)&wproj,   g_wproj);
    cudaGetSymbolAddress((void**)&wfc1,    g_wfc1);
    cudaGetSymbolAddress((void**)&wfc2,    g_wfc2);
    cudaGetSymbolAddress((void**)&btbl,    g_biastbl);

    // 0. convert weights to bf16; build attention bias table
    cvt_kernel<<<(Cq*3*Cq + 255)/256, 256>>>(w_qkv,  wqkv,  Cq*3*Cq);
    cvt_kernel<<<(Cq*Cq   + 255)/256, 256>>>(w_proj, wproj, Cq*Cq);
    cvt_kernel<<<(Cq*HIDq + 255)/256, 256>>>(w_fc1,  wfc1,  Cq*HIDq);
    cvt_kernel<<<(HIDq*Cq + 255)/256, 256>>>(w_fc2,  wfc2,  HIDq*Cq);
    bias_table_kernel<<<dim3(64, NHq), 64>>>(rel_bias, btbl);

    // 1. LN1 -> bf16
    ln_kernel<<<ROWS, 128>>>(x, gamma1, beta1, xn);

    // 2. QKV gemm -> bf16
    {
        dim3 grid((3 * Cq) / 128, ROWS / 128);
        bf16_gemm_kernel<bf16, false, false><<<grid, 256>>>(xn, wqkv, nullptr, nullptr,
                                                            qkv, ROWS, 3 * Cq, Cq);
    }

    // 3. window attention (tensor cores) -> bf16
    {
        dim3 grid(Bq * 64, NHq);
        attn_mma_kernel<<<grid, 128>>>(qkv, btbl, attnout);
    }

    // 4. proj + bias + residual(x) -> d_out (fp32)
    {
        dim3 grid(Cq / 128, ROWS / 128);
        bf16_gemm_kernel<float, true, true><<<grid, 256>>>(attnout, wproj, b_proj, x,
                                                           out, ROWS, Cq, Cq);
    }

    // 5. LN2 -> bf16
    ln_kernel<<<ROWS, 128>>>(out, gamma2, beta2, xn);

    // 6. fc1 + bias -> bf16
    {
        dim3 grid(HIDq / 128, ROWS / 128);
        bf16_gemm_kernel<bf16, true, false><<<grid, 256>>>(xn, wfc1, b_fc1, nullptr,
                                                           h1, ROWS, HIDq, Cq);
    }

    // 7. depthwise 3x3 + bias + GELU -> bf16
    {
        int total = ROWS * (HIDq / 8);
        dwconv_gelu_kernel<<<(total + 255) / 256, 256>>>(h1, w_dw, b_dw, h2);
    }

    // 8. fc2 + bias + residual(d_out) -> d_out (fp32)
    {
        dim3 grid(Cq / 128, ROWS / 128);
        bf16_gemm_kernel<float, true, true><<<grid, 256>>>(h2, wfc2, b_fc2, out,
                                                           out, ROWS, Cq, HIDq);
    }
}

// round 16
// speedup vs baseline: 3.9497x; 1.0220x over previous
#include <cuda_runtime.h>
#include <cuda_bf16.h>
#include <math.h>
#include <stdint.h>

typedef __nv_bfloat16 bf16;

// ---------------- problem constants ----------------
#define Bq    32
#define Hq    56
#define Wq    56
#define Cq    384
#define NHq   6
#define HDq   64
#define NWq   49
#define HIDq  1536
#define Ntok  (Hq*Wq)     // 3136
#define ROWS  (Bq*Ntok)   // 100352
#define LN_EPS 1e-5f

// ---------------- scratch (device globals) ----------------
__device__ bf16 g_xn[(size_t)ROWS * Cq];
__device__ bf16 g_qkv[(size_t)ROWS * 3 * Cq];
__device__ bf16 g_attnout[(size_t)ROWS * Cq];
__device__ bf16 g_h1[(size_t)ROWS * HIDq];
__device__ bf16 g_h2[(size_t)ROWS * HIDq];
__device__ bf16 g_wqkv[Cq * 3 * Cq];
__device__ bf16 g_wproj[Cq * Cq];
__device__ bf16 g_wfc1[Cq * HIDq];
__device__ bf16 g_wfc2[HIDq * Cq];
__device__ float g_biastbl[NHq * 64 * 66];

// ---------------- small helpers ----------------
__device__ __forceinline__ uint32_t smem_cast(const void* p) {
    return (uint32_t)__cvta_generic_to_shared(p);
}
__device__ __forceinline__ void cp16(uint32_t s, const void* g) {
    asm volatile("cp.async.cg.shared.global [%0], [%1], 16;\n" :: "r"(s), "l"(g));
}
__device__ __forceinline__ void cp_commit() {
    asm volatile("cp.async.commit_group;\n");
}
template<int N> __device__ __forceinline__ void cp_wait() {
    asm volatile("cp.async.wait_group %0;\n" :: "n"(N));
}
__device__ __forceinline__ void ldsm4(uint32_t* r, uint32_t a) {
    asm volatile("ldmatrix.sync.aligned.m8n8.x4.shared.b16 {%0,%1,%2,%3}, [%4];"
        : "=r"(r[0]), "=r"(r[1]), "=r"(r[2]), "=r"(r[3]) : "r"(a));
}
__device__ __forceinline__ void ldsm4t(uint32_t* r, uint32_t a) {
    asm volatile("ldmatrix.sync.aligned.m8n8.x4.trans.shared.b16 {%0,%1,%2,%3}, [%4];"
        : "=r"(r[0]), "=r"(r[1]), "=r"(r[2]), "=r"(r[3]) : "r"(a));
}
__device__ __forceinline__ void mma_bf16(float* c, const uint32_t* a, uint32_t b0, uint32_t b1) {
    asm volatile(
        "mma.sync.aligned.m16n8k16.row.col.f32.bf16.bf16.f32 "
        "{%0,%1,%2,%3}, {%4,%5,%6,%7}, {%8,%9}, {%0,%1,%2,%3};\n"
        : "+f"(c[0]), "+f"(c[1]), "+f"(c[2]), "+f"(c[3])
        : "r"(a[0]), "r"(a[1]), "r"(a[2]), "r"(a[3]), "r"(b0), "r"(b1));
}
__device__ __forceinline__ uint32_t packbf(float a, float b) {
    __nv_bfloat162 v = __float22bfloat162_rn(make_float2(a, b));
    return *(uint32_t*)&v;
}

// ---------------- merged prologue: 4 weight cvts + attention bias table ----
#define N_WQKV  (Cq * 3 * Cq)            // 442368
#define N_WPROJ (Cq * Cq)                // 147456
#define N_WFC1  (Cq * HIDq)              // 589824
#define N_WFC2  (HIDq * Cq)              // 589824
#define CVT_TOT (N_WQKV + N_WPROJ + N_WFC1 + N_WFC2)   // 1769472
#define PREP_TOT (CVT_TOT + NHq * 64 * 64)             // 1794048 = 7008*256
__global__ __launch_bounds__(256) void prep_kernel(
    const float* __restrict__ w_qkv, const float* __restrict__ w_proj,
    const float* __restrict__ w_fc1, const float* __restrict__ w_fc2,
    const float* __restrict__ rel_bias,
    bf16* __restrict__ wqkv, bf16* __restrict__ wproj,
    bf16* __restrict__ wfc1, bf16* __restrict__ wfc2,
    float* __restrict__ tbl)
{
    int i = blockIdx.x * 256 + threadIdx.x;
    if (i < N_WQKV) {
        wqkv[i] = __float2bfloat16(w_qkv[i]);
    } else if ((i -= N_WQKV) < N_WPROJ) {
        wproj[i] = __float2bfloat16(w_proj[i]);
    } else if ((i -= N_WPROJ) < N_WFC1) {
        wfc1[i] = __float2bfloat16(w_fc1[i]);
    } else if ((i -= N_WFC1) < N_WFC2) {
        wfc2[i] = __float2bfloat16(w_fc2[i]);
    } else {
        i -= N_WFC2;
        int head = i >> 12;            // /4096
        int rem  = i & 4095;
        int ii = rem >> 6, jj = rem & 63;
        float v;
        if (jj >= NWq)      v = -1e30f;
        else if (ii >= NWq) v = 0.0f;
        else {
            int dy = ii / 7 - jj / 7 + 6;
            int dx = ii % 7 - jj % 7 + 6;
            v = rel_bias[(dy * 13 + dx) * NHq + head];
        }
        tbl[head * (64 * 66) + ii * 66 + jj] = v;
    }
}

// ---------------- LayerNorm (fp32 in, bf16 out), float4 vectorized ---------
__global__ __launch_bounds__(128) void ln_kernel(
    const float* __restrict__ x, const float* __restrict__ gamma,
    const float* __restrict__ beta, bf16* __restrict__ y)
{
    int row = blockIdx.x;
    const float* xr = x + (size_t)row * Cq;
    bf16* yr = y + (size_t)row * Cq;
    int tid = threadIdx.x;

    float4 v = make_float4(0.f, 0.f, 0.f, 0.f);
    if (tid < 96) v = *(const float4*)(xr + tid * 4);
    float s  = v.x + v.y + v.z + v.w;
    float s2 = v.x*v.x + v.y*v.y + v.z*v.z + v.w*v.w;
    #pragma unroll
    for (int o = 16; o > 0; o >>= 1) {
        s  += __shfl_down_sync(0xffffffffu, s,  o);
        s2 += __shfl_down_sync(0xffffffffu, s2, o);
    }
    __shared__ float sh[8];
    int wid = tid >> 5, lid = tid & 31;
    if (lid == 0) { sh[wid] = s; sh[wid + 4] = s2; }
    __syncthreads();
    if (tid == 0) {
        float ts  = sh[0] + sh[1] + sh[2] + sh[3];
        float ts2 = sh[4] + sh[5] + sh[6] + sh[7];
        float mu = ts * (1.0f / Cq);
        float var = ts2 * (1.0f / Cq) - mu * mu;
        sh[0] = mu;
        sh[1] = rsqrtf(var + LN_EPS);
    }
    __syncthreads();
    if (tid < 96) {
        float mu = sh[0], inv = sh[1];
        float4 gm = *(const float4*)(gamma + tid * 4);
        float4 bt = *(const float4*)(beta  + tid * 4);
        float o0 = (v.x - mu) * inv * gm.x + bt.x;
        float o1 = (v.y - mu) * inv * gm.y + bt.y;
        float o2 = (v.z - mu) * inv * gm.z + bt.z;
        float o3 = (v.w - mu) * inv * gm.w + bt.w;
        uint2 pk = make_uint2(packbf(o0, o1), packbf(o2, o3));
        *(uint2*)(yr + tid * 4) = pk;
    }
}

// ---------------- bf16 tensor-core GEMM (R15-validated, unchanged) ----------
template<typename OT, bool BIAS, bool RES>
__global__ __launch_bounds__(256, 2) void bf16_gemm_kernel(
    const bf16* __restrict__ A, const bf16* __restrict__ B,
    const float* __restrict__ bias, const float* __restrict__ res,
    OT* __restrict__ C, int M, int N, int K)
{
    __shared__ __align__(16) char smem[3 * 16384];
    uint32_t sbase = smem_cast(smem);

    int tid = threadIdx.x, lane = tid & 31, warp = tid >> 5;
    int warp_m = warp & 3, warp_n = warp >> 2;   // 4x2 warp grid, 32x64 tiles
    int bm = blockIdx.y * 128, bn = blockIdx.x * 128;

    int arow0 = tid >> 2;
    int ag    = tid & 3;
    const bf16* gA0 = A + (size_t)(bm + arow0) * K + ag * 8;
    const bf16* gA1 = gA0 + (size_t)64 * K;
    uint32_t sA0 = arow0 * 64 + ((ag ^ ((arow0 >> 1) & 3)) << 4);
    int arow1 = arow0 + 64;
    uint32_t sA1 = arow1 * 64 + ((ag ^ ((arow1 >> 1) & 3)) << 4);

    int bk0 = tid >> 4;
    int bn8 = tid & 15;
    const bf16* gB0 = B + (size_t)bk0 * N + bn + bn8 * 8;
    const bf16* gB1 = gB0 + (size_t)16 * N;
    uint32_t sB0 = 8192 + bk0 * 256 + (((bn8 & 8) | ((bn8 & 7) ^ (bk0 & 7))) << 4);
    int bk1 = bk0 + 16;
    uint32_t sB1 = 8192 + bk1 * 256 + (((bn8 & 8) | ((bn8 & 7) ^ (bk1 & 7))) << 4);

    int l7 = lane & 7, lb = (lane >> 3) & 1, lh = (lane >> 4) & 1;
    int arow = warp_m * 32 + l7 + lb * 8;
    uint32_t aoff[2];
    #pragma unroll
    for (int s = 0; s < 2; s++) {
        int gg = s * 2 + lh;
        aoff[s] = arow * 64 + ((gg ^ ((arow >> 1) & 3)) << 4);
    }
    int bkl = l7 + lb * 8;
    uint32_t boff[4];
    #pragma unroll
    for (int p = 0; p < 4; p++) {
        int n8 = warp_n * 8 + p * 2 + lh;
        boff[p] = 8192 + bkl * 256 + (((n8 & 8) | ((n8 & 7) ^ (bkl & 7))) << 4);
    }

    float acc[2][8][4];
    #pragma unroll
    for (int i = 0; i < 2; i++)
        #pragma unroll
        for (int j = 0; j < 8; j++)
            #pragma unroll
            for (int r = 0; r < 4; r++) acc[i][j][r] = 0.0f;

    int T = K / 32;
    auto issue = [&](int t, int st) {
        uint32_t sb = sbase + st * 16384;
        cp16(sb + sA0, gA0 + t * 32);
        cp16(sb + sA1, gA1 + t * 32);
        cp16(sb + sB0, gB0 + (size_t)t * 32 * N);
        cp16(sb + sB1, gB1 + (size_t)t * 32 * N);
    };

    issue(0, 0); cp_commit();
    issue(1, 1); cp_commit();
    cp_wait<1>(); __syncthreads();

    for (int t = 0; t < T; t++) {
        int st = t - (t / 3) * 3;
        if (t + 2 < T) issue(t + 2, (t + 2) % 3);
        cp_commit();

        uint32_t sb = sbase + st * 16384;
        #pragma unroll
        for (int s = 0; s < 2; s++) {
            uint32_t a[2][4], b[4][4];
            #pragma unroll
            for (int mi = 0; mi < 2; mi++) ldsm4(a[mi], sb + aoff[s] + mi * 1024);
            #pragma unroll
            for (int p = 0; p < 4; p++) ldsm4t(b[p], sb + boff[p] + s * 4096);
            #pragma unroll
            for (int mi = 0; mi < 2; mi++)
                #pragma unroll
                for (int p = 0; p < 4; p++) {
                    mma_bf16(acc[mi][2*p],   a[mi], b[p][0], b[p][1]);
                    mma_bf16(acc[mi][2*p+1], a[mi], b[p][2], b[p][3]);
                }
        }
        cp_wait<1>(); __syncthreads();
    }

    int g = lane >> 2, tig = lane & 3;
    #pragma unroll
    for (int mi = 0; mi < 2; mi++) {
        int row0 = bm + warp_m * 32 + mi * 16 + g;
        #pragma unroll
        for (int ni = 0; ni < 8; ni++) {
            int col = bn + warp_n * 64 + ni * 8 + tig * 2;
            size_t off0 = (size_t)row0 * N + col;
            size_t off1 = off0 + (size_t)8 * N;
            float c0 = acc[mi][ni][0], c1 = acc[mi][ni][1];
            float c2 = acc[mi][ni][2], c3 = acc[mi][ni][3];
            if (BIAS) {
                float b0 = bias[col], b1 = bias[col + 1];
                c0 += b0; c1 += b1; c2 += b0; c3 += b1;
            }
            if (RES) {
                float2 r0 = *(const float2*)(res + off0);
                float2 r1 = *(const float2*)(res + off1);
                c0 += r0.x; c1 += r0.y; c2 += r1.x; c3 += r1.y;
            }
            if constexpr (sizeof(OT) == 4) {
                *(float2*)((float*)C + off0) = make_float2(c0, c1);
                *(float2*)((float*)C + off1) = make_float2(c2, c3);
            } else {
                *(uint32_t*)((bf16*)C + off0) = packbf(c0, c1);
                *(uint32_t*)((bf16*)C + off1) = packbf(c2, c3);
            }
        }
    }
}

// ---------------- window attention via tensor cores (R15, unchanged) --------
__global__ __launch_bounds__(128) void attn_mma_kernel(
    const bf16* __restrict__ qkv, const float* __restrict__ biastbl,
    bf16* __restrict__ out)
{
    __shared__ __align__(16) bf16 qs[64 * 72];
    __shared__ __align__(16) bf16 ks[64 * 72];
    __shared__ __align__(16) bf16 vs[64 * 72];
    __shared__ int grow[NWq];

    int win = blockIdx.x, head = blockIdx.y;
    int b = win >> 6, wi = win & 63, wy = wi >> 3, wx = wi & 7;
    int tid = threadIdx.x, lane = tid & 31, warp = tid >> 5;

    if (tid < NWq) {
        int py = tid / 7, px = tid % 7;
        grow[tid] = b * Ntok + (wy * 7 + py) * Wq + (wx * 7 + px);
    }
    for (int i = tid; i < 16 * 8 * 3; i += 128) {
        int arr = i >> 7;
        int rem = i & 127;
        int r = 48 + (rem >> 3), c8 = rem & 7;
        bf16* base = arr == 0 ? qs : (arr == 1 ? ks : vs);
        *(uint4*)&base[r * 72 + c8 * 8] = make_uint4(0, 0, 0, 0);
    }
    __syncthreads();

    for (int i = tid; i < NWq * 8; i += 128) {
        int r = i >> 3, c8 = i & 7;
        size_t gb = (size_t)grow[r] * (3 * Cq) + head * HDq + c8 * 8;
        *(uint4*)&qs[r * 72 + c8 * 8] = *(const uint4*)&qkv[gb];
        *(uint4*)&ks[r * 72 + c8 * 8] = *(const uint4*)&qkv[gb + Cq];
        *(uint4*)&vs[r * 72 + c8 * 8] = *(const uint4*)&qkv[gb + 2 * Cq];
    }
    __syncthreads();

    int g = lane >> 2, tig = lane & 3, l7 = lane & 7;
    int i0 = warp * 16;
    uint32_t qbase = smem_cast(qs), kbase = smem_cast(ks), vbase = smem_cast(vs);
    const float* bt = biastbl + head * (64 * 66);

    float sc[8][4];
    #pragma unroll
    for (int n = 0; n < 8; n++)
        #pragma unroll
        for (int r = 0; r < 4; r++) sc[n][r] = 0.0f;

    #pragma unroll
    for (int t = 0; t < 4; t++) {
        uint32_t aq[4];
        uint32_t aaddr = qbase + (uint32_t)((i0 + (lane & 15)) * 144 + (t * 16 + ((lane >> 4) << 3)) * 2);
        ldsm4(aq, aaddr);
        #pragma unroll
        for (int p = 0; p < 4; p++) {
            uint32_t bk[4];
            int m = lane >> 3;
            int nrow = (p * 2 + (m >> 1)) * 8 + l7;
            uint32_t baddr = kbase + (uint32_t)(nrow * 144 + (t * 16 + ((m & 1) << 3)) * 2);
            ldsm4(bk, baddr);
            mma_bf16(sc[p * 2],     aq, bk[0], bk[1]);
            mma_bf16(sc[p * 2 + 1], aq, bk[2], bk[3]);
        }
    }

    float m0 = -1e30f, m1 = -1e30f;
    #pragma unroll
    for (int n = 0; n < 8; n++) {
        int j = n * 8 + tig * 2;
        float2 b0 = *(const float2*)&bt[(i0 + g) * 66 + j];
        float2 b1 = *(const float2*)&bt[(i0 + g + 8) * 66 + j];
        sc[n][0] = fmaf(sc[n][0], 0.125f, b0.x);
        sc[n][1] = fmaf(sc[n][1], 0.125f, b0.y);
        sc[n][2] = fmaf(sc[n][2], 0.125f, b1.x);
        sc[n][3] = fmaf(sc[n][3], 0.125f, b1.y);
        m0 = fmaxf(m0, fmaxf(sc[n][0], sc[n][1]));
        m1 = fmaxf(m1, fmaxf(sc[n][2], sc[n][3]));
    }
    #pragma unroll
    for (int o = 1; o < 4; o <<= 1) {
        m0 = fmaxf(m0, __shfl_xor_sync(0xffffffffu, m0, o));
        m1 = fmaxf(m1, __shfl_xor_sync(0xffffffffu, m1, o));
    }
    float s0 = 0.0f, s1 = 0.0f;
    #pragma unroll
    for (int n = 0; n < 8; n++) {
        sc[n][0] = __expf(sc[n][0] - m0);
        sc[n][1] = __expf(sc[n][1] - m0);
        sc[n][2] = __expf(sc[n][2] - m1);
        sc[n][3] = __expf(sc[n][3] - m1);
        s0 += sc[n][0] + sc[n][1];
        s1 += sc[n][2] + sc[n][3];
    }
    #pragma unroll
    for (int o = 1; o < 4; o <<= 1) {
        s0 += __shfl_xor_sync(0xffffffffu, s0, o);
        s1 += __shfl_xor_sync(0xffffffffu, s1, o);
    }
    float inv0 = 1.0f / s0, inv1 = 1.0f / s1;

    uint32_t pa[4][4];
    #pragma unroll
    for (int t = 0; t < 4; t++) {
        pa[t][0] = packbf(sc[2 * t][0] * inv0,     sc[2 * t][1] * inv0);
        pa[t][1] = packbf(sc[2 * t][2] * inv1,     sc[2 * t][3] * inv1);
        pa[t][2] = packbf(sc[2 * t + 1][0] * inv0, sc[2 * t + 1][1] * inv0);
        pa[t][3] = packbf(sc[2 * t + 1][2] * inv1, sc[2 * t + 1][3] * inv1);
    }

    float oa[8][4];
    #pragma unroll
    for (int n = 0; n < 8; n++)
        #pragma unroll
        for (int r = 0; r < 4; r++) oa[n][r] = 0.0f;

    int lb = (lane >> 3) & 1, lh = (lane >> 4) & 1;
    #pragma unroll
    for (int t = 0; t < 4; t++) {
        #pragma unroll
        for (int p = 0; p < 4; p++) {
            uint32_t bv[4];
            uint32_t vaddr = vbase + (uint32_t)((t * 16 + l7 + lb * 8) * 144 + (p * 16 + lh * 8) * 2);
            ldsm4t(bv, vaddr);
            mma_bf16(oa[p * 2],     pa[t], bv[0], bv[1]);
            mma_bf16(oa[p * 2 + 1], pa[t], bv[2], bv[3]);
        }
    }

    int iA = i0 + g, iB = iA + 8;
    bool wA = iA < NWq, wB = iB < NWq;
    #pragma unroll
    for (int n = 0; n < 8; n++) {
        int col = head * HDq + n * 8 + tig * 2;
        if (wA) *(uint32_t*)&out[(size_t)grow[iA] * Cq + col] = packbf(oa[n][0], oa[n][1]);
        if (wB) *(uint32_t*)&out[(size_t)grow[iB] * Cq + col] = packbf(oa[n][2], oa[n][3]);
    }
}

// ---------------- depthwise 3x3 + bias + GELU: 2 y-pixels per thread --------
__global__ __launch_bounds__(256) void dwconv_gelu_kernel(
    const bf16* __restrict__ h1, const float* __restrict__ w,
    const float* __restrict__ bias, bf16* __restrict__ h2)
{
    int idx = blockIdx.x * 256 + threadIdx.x;     // (pixel-pair, c8)
    int c8  = idx % (HIDq / 8);
    int pp  = idx / (HIDq / 8);
    int xq = pp % Wq;
    int t  = pp / Wq;
    int yy = t % (Hq / 2);
    int bq = t / (Hq / 2);
    int y0 = yy * 2, y1 = y0 + 1;
    int c = c8 * 8;

    float a0[8], a1[8];
    #pragma unroll
    for (int i = 0; i < 8; i++) { float bv = bias[c + i]; a0[i] = bv; a1[i] = bv; }

    #pragma unroll
    for (int ry = 0; ry < 4; ry++) {
        int gy = y0 - 1 + ry;
        if (gy < 0 || gy >= Hq) continue;
        #pragma unroll
        for (int dx = -1; dx <= 1; dx++) {
            int xx = xq + dx;
            if (xx < 0 || xx >= Wq) continue;
            size_t src = ((size_t)(bq * Ntok + gy * Wq + xx)) * HIDq + c;
            uint4 raw = *(const uint4*)(h1 + src);
            const bf16* pv = (const bf16*)&raw;
            if (ry < 3) {                       // contributes to out y0, row=ry
                int wk = ry * 3 + (dx + 1);
                #pragma unroll
                for (int i = 0; i < 8; i++)
                    a0[i] = fmaf(__bfloat162float(pv[i]), w[(c + i) * 9 + wk], a0[i]);
            }
            if (ry > 0) {                       // contributes to out y1, row=ry-1
                int wk = (ry - 1) * 3 + (dx + 1);
                #pragma unroll
                for (int i = 0; i < 8; i++)
                    a1[i] = fmaf(__bfloat162float(pv[i]), w[(c + i) * 9 + wk], a1[i]);
            }
        }
    }
    const float is2 = 0.70710678118654752f;
    uint4 o0, o1;
    bf16* p0 = (bf16*)&o0;
    bf16* p1 = (bf16*)&o1;
    #pragma unroll
    for (int i = 0; i < 8; i++) {
        float v0 = 0.5f * a0[i] * (1.0f + erff(a0[i] * is2));
        float v1 = 0.5f * a1[i] * (1.0f + erff(a1[i] * is2));
        p0[i] = __float2bfloat16(v0);
        p1[i] = __float2bfloat16(v1);
    }
    size_t d0 = ((size_t)(bq * Ntok + y0 * Wq + xq)) * HIDq + c;
    *(uint4*)(h2 + d0) = o0;
    *(uint4*)(h2 + d0 + (size_t)Wq * HIDq) = o1;
}

// ---------------- launch ----------------------------------------------------
extern "C" void kernel_launch(void* const* d_in, const int* in_sizes, int n_in,
                              void* d_out, int out_size)
{
    const float* x        = (const float*)d_in[0];
    const float* gamma1   = (const float*)d_in[1];
    const float* beta1    = (const float*)d_in[2];
    const float* w_qkv    = (const float*)d_in[3];
    const float* w_proj   = (const float*)d_in[4];
    const float* b_proj   = (const float*)d_in[5];
    const float* rel_bias = (const float*)d_in[6];
    const float* gamma2   = (const float*)d_in[7];
    const float* beta2    = (const float*)d_in[8];
    const float* w_fc1    = (const float*)d_in[9];
    const float* b_fc1    = (const float*)d_in[10];
    const float* w_dw     = (const float*)d_in[11];
    const float* b_dw     = (const float*)d_in[12];
    const float* w_fc2    = (const float*)d_in[13];
    const float* b_fc2    = (const float*)d_in[14];
    float* out = (float*)d_out;

    bf16 *xn, *qkv, *attnout, *h1, *h2, *wqkv, *wproj, *wfc1, *wfc2;
    float* btbl;
    cudaGetSymbolAddress((void**)&xn,      g_xn);
    cudaGetSymbolAddress((void**)&qkv,     g_qkv);
    cudaGetSymbolAddress((void**)&attnout, g_attnout);
    cudaGetSymbolAddress((void**)&h1,      g_h1);
    cudaGetSymbolAddress((void**)&h2,      g_h2);
    cudaGetSymbolAddress((void**)&wqkv,    g_wqkv);
    cudaGetSymbolAddress((void**)&wproj,   g_wproj);
    cudaGetSymbolAddress((void**)&wfc1,    g_wfc1);
    cudaGetSymbolAddress((void**)&wfc2,    g_wfc2);
    cudaGetSymbolAddress((void**)&btbl,    g_biastbl);

    // 0. merged prologue (weights -> bf16, bias table)
    prep_kernel<<<PREP_TOT / 256, 256>>>(w_qkv, w_proj, w_fc1, w_fc2, rel_bias,
                                         wqkv, wproj, wfc1, wfc2, btbl);

    // 1. LN1 -> bf16
    ln_kernel<<<ROWS, 128>>>(x, gamma1, beta1, xn);

    // 2. QKV gemm -> bf16
    {
        dim3 grid((3 * Cq) / 128, ROWS / 128);
        bf16_gemm_kernel<bf16, false, false><<<grid, 256>>>(xn, wqkv, nullptr, nullptr,
                                                            qkv, ROWS, 3 * Cq, Cq);
    }

    // 3. window attention (tensor cores) -> bf16
    {
        dim3 grid(Bq * 64, NHq);
        attn_mma_kernel<<<grid, 128>>>(qkv, btbl, attnout);
    }

    // 4. proj + bias + residual(x) -> d_out (fp32)
    {
        dim3 grid(Cq / 128, ROWS / 128);
        bf16_gemm_kernel<float, true, true><<<grid, 256>>>(attnout, wproj, b_proj, x,
                                                           out, ROWS, Cq, Cq);
    }

    // 5. LN2 -> bf16
    ln_kernel<<<ROWS, 128>>>(out, gamma2, beta2, xn);

    // 6. fc1 + bias -> bf16
    {
        dim3 grid(HIDq / 128, ROWS / 128);
        bf16_gemm_kernel<bf16, true, false><<<grid, 256>>>(xn, wfc1, b_fc1, nullptr,
                                                           h1, ROWS, HIDq, Cq);
    }

    // 7. depthwise 3x3 + bias + GELU -> bf16 (2 y-pixels per thread)
    {
        int total = (ROWS / 2) * (HIDq / 8);
        dwconv_gelu_kernel<<<total / 256, 256>>>(h1, w_dw, b_dw, h2);
    }

    // 8. fc2 + bias + residual(d_out) -> d_out (fp32)
    {
        dim3 grid(Cq / 128, ROWS / 128);
        bf16_gemm_kernel<float, true, true><<<grid, 256>>>(h2, wfc2, b_fc2, out,
                                                           out, ROWS, Cq, HIDq);
    }
}